// round 5
// baseline (speedup 1.0000x reference)
#include <cuda_runtime.h>
#include <cuda_bf16.h>
#include <cstdint>

typedef __nv_bfloat16 bf16;

constexpr int BSZ = 8, SEQ = 2048, DIM = 768;
constexpr int MTOT = BSZ * SEQ;            // 16384

// CTA tile 256x128, BK=32. Padded 80B rows for conflict-free ldmatrix.
constexpr int ROWB   = 80;
constexpr int A_HI   = 0;                  // 256 x 80 = 20480
constexpr int A_LO   = 20480;
constexpr int B_HI   = 40960;              // 128 x 80 = 10240
constexpr int B_LO   = 51200;
constexpr int STAGEB = 61440;
constexpr int SMEMSZ = 2 * STAGEB;         // 122880 (covers epi2 staging 66048)

// ---------------- static device scratch (allocation-free rule) --------------
__device__ bf16 g_xh[(size_t)MTOT * DIM];
__device__ bf16 g_xl[(size_t)MTOT * DIM];
__device__ bf16 g_wth[3][DIM * DIM];
__device__ bf16 g_wtl[3][DIM * DIM];
__device__ bf16 g_qh[(size_t)MTOT * DIM];
__device__ bf16 g_ql[(size_t)MTOT * DIM];
__device__ bf16 g_kh[(size_t)MTOT * DIM];
__device__ bf16 g_kl[(size_t)MTOT * DIM];
__device__ bf16 g_vth[(size_t)MTOT * DIM];   // V^T per batch: [b][768][2048]
__device__ bf16 g_vtl[(size_t)MTOT * DIM];
__device__ float g_s[(size_t)BSZ * SEQ * SEQ];
__device__ bf16 g_ph[(size_t)BSZ * SEQ * SEQ];
__device__ bf16 g_pl[(size_t)BSZ * SEQ * SEQ];

// ---------------- PTX helpers ----------------------------------------------
__device__ __forceinline__ uint32_t smem_u32(const void* p) {
    uint32_t a;
    asm("{ .reg .u64 t; cvta.to.shared.u64 t, %1; cvt.u32.u64 %0, t; }"
        : "=r"(a) : "l"(p));
    return a;
}

__device__ __forceinline__ void ldmx4(uint32_t* r, uint32_t a) {
    asm volatile("ldmatrix.sync.aligned.m8n8.x4.shared.b16 {%0,%1,%2,%3}, [%4];"
                 : "=r"(r[0]), "=r"(r[1]), "=r"(r[2]), "=r"(r[3]) : "r"(a));
}

__device__ __forceinline__ void mma_bf16(float* c, const uint32_t* a, const uint32_t* b) {
    asm volatile(
        "mma.sync.aligned.m16n8k16.row.col.f32.bf16.bf16.f32 "
        "{%0,%1,%2,%3}, {%4,%5,%6,%7}, {%8,%9}, {%0,%1,%2,%3};"
        : "+f"(c[0]), "+f"(c[1]), "+f"(c[2]), "+f"(c[3])
        : "r"(a[0]), "r"(a[1]), "r"(a[2]), "r"(a[3]), "r"(b[0]), "r"(b[1]));
}

__device__ __forceinline__ void cpasync16(uint32_t s, const void* g) {
    asm volatile("cp.async.cg.shared.global [%0], [%1], 16;" :: "r"(s), "l"(g));
}

// ---------------------------------------------------------------------------
// HMMA GEMM: C[M,N] = A * B^T, split-bf16 (3 passes: AhBh + AhBl + AlBh).
// A: [M,K] row-major hi/lo.  B: [N,K] row-major hi/lo.  fp32 accum.
// CTA tile 256x128xBK32, 256 threads, warp grid 4(M) x 2(N), warp tile 64x64.
// 85 B smem-read per MMA -> tensor-pipe bound (smem crossbar no longer binds).
// EPI 0: fp32 C (batched).  EPI 1: bf16 hi/lo C.  EPI 2: hi/lo + V->V^T.
// ---------------------------------------------------------------------------
template <int EPI>
__global__ void __launch_bounds__(256, 1)
gemm_mma(const bf16* __restrict__ Ah, const bf16* __restrict__ Al,
         const bf16* __restrict__ Bh, const bf16* __restrict__ Bl,
         void* __restrict__ O0, void* __restrict__ O1,
         int K, long batchA, long batchB, long batchC, int ldC)
{
    extern __shared__ char smem[];
    const int tid = threadIdx.x, lane = tid & 31, wid = tid >> 5;
    const int z = blockIdx.z;
    const int m0 = blockIdx.y * 256, n0 = blockIdx.x * 128;
    const int warp_m = wid & 3, warp_n = wid >> 2;

    const char* pAh = (const char*)(Ah + (size_t)z * batchA);
    const char* pAl = (const char*)(Al + (size_t)z * batchA);
    const char* pBh = (const char*)(Bh + (size_t)z * batchB);
    const char* pBl = (const char*)(Bl + (size_t)z * batchB);

    const uint32_t sb = smem_u32(smem);
    const uint32_t rowbytes = (uint32_t)K * 2;

    float acc[4][8][4];
#pragma unroll
    for (int t = 0; t < 4; t++)
#pragma unroll
        for (int j = 0; j < 8; j++)
#pragma unroll
            for (int c = 0; c < 4; c++) acc[t][j][c] = 0.0f;

    const int nch = K >> 5;

    // loader indices (per-thread): row = c>>2, 16B seg = (c&3)*16
#define ISSUE(kc, buf)                                                           \
    {                                                                            \
        uint32_t s0 = sb + (buf) * STAGEB;                                       \
        uint32_t kcb = (uint32_t)(kc) * 64;                                      \
        _Pragma("unroll")                                                        \
        for (int i = 0; i < 4; i++) {                                            \
            int c = tid + i * 256;                                               \
            int r = c >> 2, sg = (c & 3) * 16;                                   \
            size_t go = (size_t)(m0 + r) * rowbytes + kcb + sg;                  \
            uint32_t so = r * ROWB + sg;                                         \
            cpasync16(s0 + A_HI + so, pAh + go);                                 \
            cpasync16(s0 + A_LO + so, pAl + go);                                 \
        }                                                                        \
        _Pragma("unroll")                                                        \
        for (int i = 0; i < 2; i++) {                                            \
            int c = tid + i * 256;                                               \
            int r = c >> 2, sg = (c & 3) * 16;                                   \
            size_t go = (size_t)(n0 + r) * rowbytes + kcb + sg;                  \
            uint32_t so = r * ROWB + sg;                                         \
            cpasync16(s0 + B_HI + so, pBh + go);                                 \
            cpasync16(s0 + B_LO + so, pBl + go);                                 \
        }                                                                        \
    }

    ISSUE(0, 0);
    asm volatile("cp.async.commit_group;" ::: "memory");

    for (int kc = 0; kc < nch; kc++) {
        if (kc + 1 < nch) ISSUE(kc + 1, (kc + 1) & 1);
        asm volatile("cp.async.commit_group;" ::: "memory");
        asm volatile("cp.async.wait_group 1;" ::: "memory");
        __syncthreads();

        const uint32_t sA = sb + (kc & 1) * STAGEB;
#pragma unroll
        for (int ks = 0; ks < 2; ks++) {
            const uint32_t kb = ks * 32;   // byte offset of k16 slice
            uint32_t afh[4][4], afl[4][4];

            // A frags: row = warp_m*64 + t*16 + (lane&15), k-half = (lane>>4)*8
            const uint32_t aoff = (warp_m * 64 + (lane & 15)) * ROWB + kb + (lane >> 4) * 16;
#pragma unroll
            for (int t = 0; t < 4; t++) {
                uint32_t ad = sA + aoff + t * 16 * ROWB;
                ldmx4(afh[t], ad);
                ldmx4(afl[t], ad + A_LO);
            }

            // B frags per column-pair; 24 MMAs per pair (B reuse 12x)
            const uint32_t boff = (warp_n * 64 + (lane >> 4) * 8 + (lane & 7)) * ROWB +
                                  kb + ((lane >> 3) & 1) * 16;
#pragma unroll
            for (int jp = 0; jp < 4; jp++) {
                uint32_t bd = sA + B_HI + boff + jp * 16 * ROWB;
                uint32_t rh[4], rl[4];
                ldmx4(rh, bd);
                ldmx4(rl, bd + 10240);
                const int j0 = jp * 2, j1 = jp * 2 + 1;
#pragma unroll
                for (int t = 0; t < 4; t++) {
                    mma_bf16(acc[t][j0], afh[t], rh + 0);
                    mma_bf16(acc[t][j1], afh[t], rh + 2);
                }
#pragma unroll
                for (int t = 0; t < 4; t++) {
                    mma_bf16(acc[t][j0], afh[t], rl + 0);
                    mma_bf16(acc[t][j1], afh[t], rl + 2);
                }
#pragma unroll
                for (int t = 0; t < 4; t++) {
                    mma_bf16(acc[t][j0], afl[t], rh + 0);
                    mma_bf16(acc[t][j1], afl[t], rh + 2);
                }
            }
        }
        __syncthreads();
    }
#undef ISSUE

    // ---------------- epilogue ----------------
    const int rbase = warp_m * 64 + (lane >> 2);
    const int cbase = warp_n * 64 + (lane & 3) * 2;

    if (EPI == 0) {
        float* C = (float*)O0 + (size_t)z * batchC;
#pragma unroll
        for (int t = 0; t < 4; t++)
#pragma unroll
            for (int j = 0; j < 8; j++) {
                int rr = m0 + rbase + t * 16;
                int cc = n0 + cbase + j * 8;
                *(float2*)(C + (size_t)rr * ldC + cc) =
                    make_float2(acc[t][j][0], acc[t][j][1]);
                *(float2*)(C + (size_t)(rr + 8) * ldC + cc) =
                    make_float2(acc[t][j][2], acc[t][j][3]);
            }
    } else if (EPI == 1) {
        bf16* Oh = (bf16*)O0;
        bf16* Ol = (bf16*)O1;
#pragma unroll
        for (int t = 0; t < 4; t++)
#pragma unroll
            for (int j = 0; j < 8; j++)
#pragma unroll
                for (int h = 0; h < 2; h++) {
                    int rr = m0 + rbase + t * 16 + h * 8;
                    int cc = n0 + cbase + j * 8;
                    float x0 = acc[t][j][h * 2 + 0], x1 = acc[t][j][h * 2 + 1];
                    bf16 h0 = __float2bfloat16(x0), h1 = __float2bfloat16(x1);
                    bf16 l0 = __float2bfloat16(x0 - __bfloat162float(h0));
                    bf16 l1 = __float2bfloat16(x1 - __bfloat162float(h1));
                    __nv_bfloat162 hp; hp.x = h0; hp.y = h1;
                    __nv_bfloat162 lp; lp.x = l0; lp.y = l1;
                    *(__nv_bfloat162*)(Oh + (size_t)rr * ldC + cc) = hp;
                    *(__nv_bfloat162*)(Ol + (size_t)rr * ldC + cc) = lp;
                }
    } else {
        // EPI 2: V -> V^T.  Stage 64 n-cols x 256 m-rows fp32 in smem per half.
        float* st = (float*)smem;
        bf16* Oh = (bf16*)O0;
        bf16* Ol = (bf16*)O1;
#pragma unroll
        for (int half = 0; half < 2; half++) {
            if (warp_n == half) {
                const int ccl = (lane & 3) * 2;    // local col base within half
#pragma unroll
                for (int t = 0; t < 4; t++)
#pragma unroll
                    for (int j = 0; j < 8; j++)
#pragma unroll
                        for (int h = 0; h < 2; h++) {
                            int rr = rbase + t * 16 + h * 8;   // 0..255
                            int cc = ccl + j * 8;              // 0..63
                            st[(size_t)cc * 258 + rr]       = acc[t][j][h * 2 + 0];
                            st[(size_t)(cc + 1) * 258 + rr] = acc[t][j][h * 2 + 1];
                        }
            }
            __syncthreads();
            for (int idx = tid; idx < 64 * 256; idx += 256) {
                int nl = idx >> 8, ml = idx & 255;
                int mg = m0 + ml;
                int b = mg >> 11, mloc = mg & 2047;
                int ng = n0 + half * 64 + nl;
                float x = st[(size_t)nl * 258 + ml];
                bf16 h = __float2bfloat16(x);
                bf16 l = __float2bfloat16(x - __bfloat162float(h));
                size_t o = (size_t)b * DIM * SEQ + (size_t)ng * SEQ + mloc;
                Oh[o] = h;
                Ol[o] = l;
            }
            __syncthreads();
        }
    }
}

// ---------------- prep kernels ----------------------------------------------
__global__ void split_kernel(const float* __restrict__ X,
                             bf16* __restrict__ H, bf16* __restrict__ L, int n)
{
    int i = blockIdx.x * 256 + threadIdx.x;
    if (i < n) {
        float x = X[i];
        bf16 h = __float2bfloat16(x);
        H[i] = h;
        L[i] = __float2bfloat16(x - __bfloat162float(h));
    }
}

__global__ void wsplit_kernel(const float* __restrict__ W,
                              bf16* __restrict__ TH, bf16* __restrict__ TL)
{
    int i = blockIdx.x * 256 + threadIdx.x;   // out idx f*DIM + d
    int f = i / DIM, d = i % DIM;
    float x = W[d * DIM + f];
    bf16 h = __float2bfloat16(x);
    TH[i] = h;
    TL[i] = __float2bfloat16(x - __bfloat162float(h));
}

// ---------------- softmax: S fp32 -> P split bf16 ---------------------------
__global__ void __launch_bounds__(256)
softmax_kernel(const float* __restrict__ S,
               bf16* __restrict__ Ph, bf16* __restrict__ Pl)
{
    const int row = blockIdx.x;
    const float* p = S + (size_t)row * SEQ;
    const int tid = threadIdx.x;

    float v[8];
    float m = -1e30f;
#pragma unroll
    for (int i = 0; i < 8; i++) {
        v[i] = p[tid + i * 256];
        m = fmaxf(m, v[i]);
    }

    __shared__ float red[256];
    red[tid] = m;
    __syncthreads();
#pragma unroll
    for (int s = 128; s > 0; s >>= 1) {
        if (tid < s) red[tid] = fmaxf(red[tid], red[tid + s]);
        __syncthreads();
    }
    m = red[0];
    __syncthreads();

    float sum = 0.0f;
#pragma unroll
    for (int i = 0; i < 8; i++) {
        v[i] = expf(v[i] - m);
        sum += v[i];
    }
    red[tid] = sum;
    __syncthreads();
#pragma unroll
    for (int s = 128; s > 0; s >>= 1) {
        if (tid < s) red[tid] += red[tid + s];
        __syncthreads();
    }
    const float inv = 1.0f / red[0];
#pragma unroll
    for (int i = 0; i < 8; i++) {
        float pr = v[i] * inv;
        bf16 h = __float2bfloat16(pr);
        size_t o = (size_t)row * SEQ + tid + i * 256;
        Ph[o] = h;
        Pl[o] = __float2bfloat16(pr - __bfloat162float(h));
    }
}

// ---------------------------------------------------------------------------
extern "C" void kernel_launch(void* const* d_in, const int* in_sizes, int n_in,
                              void* d_out, int out_size)
{
    const float* X  = (const float*)d_in[0];
    const float* Wq = (const float*)d_in[1];
    const float* Wk = (const float*)d_in[2];
    const float* Wv = (const float*)d_in[3];
    float* out = (float*)d_out;

    bf16 *xh, *xl, *wth, *wtl, *qh, *ql, *kh, *kl, *vth, *vtl, *ph, *pl;
    float* s;
    cudaGetSymbolAddress((void**)&xh, g_xh);
    cudaGetSymbolAddress((void**)&xl, g_xl);
    cudaGetSymbolAddress((void**)&wth, g_wth);
    cudaGetSymbolAddress((void**)&wtl, g_wtl);
    cudaGetSymbolAddress((void**)&qh, g_qh);
    cudaGetSymbolAddress((void**)&ql, g_ql);
    cudaGetSymbolAddress((void**)&kh, g_kh);
    cudaGetSymbolAddress((void**)&kl, g_kl);
    cudaGetSymbolAddress((void**)&vth, g_vth);
    cudaGetSymbolAddress((void**)&vtl, g_vtl);
    cudaGetSymbolAddress((void**)&ph, g_ph);
    cudaGetSymbolAddress((void**)&pl, g_pl);
    cudaGetSymbolAddress((void**)&s, g_s);

    cudaFuncSetAttribute(gemm_mma<0>, cudaFuncAttributeMaxDynamicSharedMemorySize, SMEMSZ);
    cudaFuncSetAttribute(gemm_mma<1>, cudaFuncAttributeMaxDynamicSharedMemorySize, SMEMSZ);
    cudaFuncSetAttribute(gemm_mma<2>, cudaFuncAttributeMaxDynamicSharedMemorySize, SMEMSZ);

    const int nx = MTOT * DIM;
    split_kernel<<<nx / 256, 256>>>(X, xh, xl, nx);
    wsplit_kernel<<<(DIM * DIM) / 256, 256>>>(Wq, wth + 0 * DIM * DIM, wtl + 0 * DIM * DIM);
    wsplit_kernel<<<(DIM * DIM) / 256, 256>>>(Wk, wth + 1 * DIM * DIM, wtl + 1 * DIM * DIM);
    wsplit_kernel<<<(DIM * DIM) / 256, 256>>>(Wv, wth + 2 * DIM * DIM, wtl + 2 * DIM * DIM);

    // Projections: [16384,768] = X * (W^T)^T
    dim3 gp(DIM / 128, MTOT / 256, 1);
    gemm_mma<1><<<gp, 256, SMEMSZ>>>(xh, xl, wth + 0 * DIM * DIM, wtl + 0 * DIM * DIM,
                                     qh, ql, DIM, 0, 0, 0, DIM);
    gemm_mma<1><<<gp, 256, SMEMSZ>>>(xh, xl, wth + 1 * DIM * DIM, wtl + 1 * DIM * DIM,
                                     kh, kl, DIM, 0, 0, 0, DIM);
    gemm_mma<2><<<gp, 256, SMEMSZ>>>(xh, xl, wth + 2 * DIM * DIM, wtl + 2 * DIM * DIM,
                                     vth, vtl, DIM, 0, 0, 0, 0);

    // Scores: per batch S = Q * K^T, [2048,2048], K=768
    dim3 gs(SEQ / 128, SEQ / 256, BSZ);
    gemm_mma<0><<<gs, 256, SMEMSZ>>>(qh, ql, kh, kl, s, nullptr, DIM,
                                     (long)SEQ * DIM, (long)SEQ * DIM,
                                     (long)SEQ * SEQ, SEQ);

    softmax_kernel<<<BSZ * SEQ, 256>>>(s, ph, pl);

    // Out: per batch O = P * (V^T)^T, [2048,768], K=2048
    dim3 go(DIM / 128, SEQ / 256, BSZ);
    gemm_mma<0><<<go, 256, SMEMSZ>>>(ph, pl, vth, vtl, out, nullptr, SEQ,
                                     (long)SEQ * SEQ, (long)DIM * SEQ,
                                     (long)SEQ * DIM, DIM);
}

// round 6
// speedup vs baseline: 1.0999x; 1.0999x over previous
#include <cuda_runtime.h>
#include <cuda_bf16.h>
#include <cstdint>

typedef __nv_bfloat16 bf16;

constexpr int BSZ = 8, SEQ = 2048, DIM = 768;
constexpr int MTOT = BSZ * SEQ;            // 16384

// CTA tile 128x128, BK=32. Padded 80B rows (64B data + 16B pad) for ldmatrix.
constexpr int ROWB   = 80;
constexpr int A_HI   = 0;                  // 128 x 80 = 10240 per tile
constexpr int A_LO   = 10240;
constexpr int B_HI   = 20480;
constexpr int B_LO   = 30720;
constexpr int STAGEB = 40960;
constexpr int SMEMSZ = 2 * STAGEB;         // 81920 (covers epi2 staging 66048)

// ---------------- static device scratch (allocation-free rule) --------------
__device__ bf16 g_xh[(size_t)MTOT * DIM];
__device__ bf16 g_xl[(size_t)MTOT * DIM];
__device__ bf16 g_wth[3][DIM * DIM];
__device__ bf16 g_wtl[3][DIM * DIM];
__device__ bf16 g_qh[(size_t)MTOT * DIM];
__device__ bf16 g_ql[(size_t)MTOT * DIM];
__device__ bf16 g_kh[(size_t)MTOT * DIM];
__device__ bf16 g_kl[(size_t)MTOT * DIM];
__device__ bf16 g_vth[(size_t)MTOT * DIM];   // V^T per batch: [b][768][2048]
__device__ bf16 g_vtl[(size_t)MTOT * DIM];
__device__ float g_s[(size_t)BSZ * SEQ * SEQ];
__device__ bf16 g_ph[(size_t)BSZ * SEQ * SEQ];
__device__ bf16 g_pl[(size_t)BSZ * SEQ * SEQ];

// ---------------- PTX helpers ----------------------------------------------
__device__ __forceinline__ uint32_t smem_u32(const void* p) {
    uint32_t a;
    asm("{ .reg .u64 t; cvta.to.shared.u64 t, %1; cvt.u32.u64 %0, t; }"
        : "=r"(a) : "l"(p));
    return a;
}

__device__ __forceinline__ void ldmx4(uint32_t* r, uint32_t a) {
    asm volatile("ldmatrix.sync.aligned.m8n8.x4.shared.b16 {%0,%1,%2,%3}, [%4];"
                 : "=r"(r[0]), "=r"(r[1]), "=r"(r[2]), "=r"(r[3]) : "r"(a));
}

__device__ __forceinline__ void mma_bf16(float* c, const uint32_t* a, const uint32_t* b) {
    asm volatile(
        "mma.sync.aligned.m16n8k16.row.col.f32.bf16.bf16.f32 "
        "{%0,%1,%2,%3}, {%4,%5,%6,%7}, {%8,%9}, {%0,%1,%2,%3};"
        : "+f"(c[0]), "+f"(c[1]), "+f"(c[2]), "+f"(c[3])
        : "r"(a[0]), "r"(a[1]), "r"(a[2]), "r"(a[3]), "r"(b[0]), "r"(b[1]));
}

__device__ __forceinline__ void cpasync16(uint32_t s, const void* g) {
    asm volatile("cp.async.cg.shared.global [%0], [%1], 16;" :: "r"(s), "l"(g));
}

// ---------------------------------------------------------------------------
// HMMA GEMM: C[M,N] = A * B^T, split-bf16 (3 passes: AhBh + AhBl + AlBh).
// A: [M,K] row-major hi/lo.  B: [N,K] row-major hi/lo.  fp32 accum.
// CTA tile 128x128xBK32, 128 threads, warp grid 2(M) x 2(N), warp tile 64x64.
// 2 CTAs/SM: cross-CTA overlap hides load/sync bubbles; 85 B smem-read/MMA.
// EPI 0: fp32 C (batched).  EPI 1: bf16 hi/lo C.  EPI 2: hi/lo + V->V^T.
// ---------------------------------------------------------------------------
template <int EPI>
__global__ void __launch_bounds__(128, 2)
gemm_mma(const bf16* __restrict__ Ah, const bf16* __restrict__ Al,
         const bf16* __restrict__ Bh, const bf16* __restrict__ Bl,
         void* __restrict__ O0, void* __restrict__ O1,
         int K, long batchA, long batchB, long batchC, int ldC)
{
    extern __shared__ char smem[];
    const int tid = threadIdx.x, lane = tid & 31, wid = tid >> 5;
    const int z = blockIdx.z;
    const int m0 = blockIdx.y * 128, n0 = blockIdx.x * 128;
    const int warp_m = wid & 1, warp_n = wid >> 1;

    const char* pAh = (const char*)(Ah + (size_t)z * batchA);
    const char* pAl = (const char*)(Al + (size_t)z * batchA);
    const char* pBh = (const char*)(Bh + (size_t)z * batchB);
    const char* pBl = (const char*)(Bl + (size_t)z * batchB);

    const uint32_t sb = smem_u32(smem);
    const uint32_t rowbytes = (uint32_t)K * 2;

    float acc[4][8][4];
#pragma unroll
    for (int t = 0; t < 4; t++)
#pragma unroll
        for (int j = 0; j < 8; j++)
#pragma unroll
            for (int c = 0; c < 4; c++) acc[t][j][c] = 0.0f;

    const int nch = K >> 5;

    // loader: per tile 512 16B chunks (128 rows x 4 segs); 4 iters x 128 thr
#define ISSUE(kc, buf)                                                           \
    {                                                                            \
        uint32_t s0 = sb + (buf) * STAGEB;                                       \
        uint32_t kcb = (uint32_t)(kc) * 64;                                      \
        _Pragma("unroll")                                                        \
        for (int i = 0; i < 4; i++) {                                            \
            int c = tid + i * 128;                                               \
            int r = c >> 2, sg = (c & 3) * 16;                                   \
            size_t goA = (size_t)(m0 + r) * rowbytes + kcb + sg;                 \
            size_t goB = (size_t)(n0 + r) * rowbytes + kcb + sg;                 \
            uint32_t so = r * ROWB + sg;                                         \
            cpasync16(s0 + A_HI + so, pAh + goA);                                \
            cpasync16(s0 + A_LO + so, pAl + goA);                                \
            cpasync16(s0 + B_HI + so, pBh + goB);                                \
            cpasync16(s0 + B_LO + so, pBl + goB);                                \
        }                                                                        \
    }

    ISSUE(0, 0);
    asm volatile("cp.async.commit_group;" ::: "memory");

    for (int kc = 0; kc < nch; kc++) {
        if (kc + 1 < nch) ISSUE(kc + 1, (kc + 1) & 1);
        asm volatile("cp.async.commit_group;" ::: "memory");
        asm volatile("cp.async.wait_group 1;" ::: "memory");
        __syncthreads();

        const uint32_t sA = sb + (kc & 1) * STAGEB;
#pragma unroll
        for (int ks = 0; ks < 2; ks++) {
            const uint32_t kb = ks * 32;   // byte offset of k16 slice
            uint32_t afh[4][4], afl[4][4];

            // A frags: row = warp_m*64 + t*16 + (lane&15), k-half = (lane>>4)*8
            const uint32_t aoff = (warp_m * 64 + (lane & 15)) * ROWB + kb + (lane >> 4) * 16;
#pragma unroll
            for (int t = 0; t < 4; t++) {
                uint32_t ad = sA + aoff + t * 16 * ROWB;
                ldmx4(afh[t], ad);
                ldmx4(afl[t], ad + 10240);
            }

            // B frags per column-pair; 24 MMAs per pair (B reuse 12x)
            const uint32_t boff = (warp_n * 64 + (lane >> 4) * 8 + (lane & 7)) * ROWB +
                                  kb + ((lane >> 3) & 1) * 16;
#pragma unroll
            for (int jp = 0; jp < 4; jp++) {
                uint32_t bd = sA + B_HI + boff + jp * 16 * ROWB;
                uint32_t rh[4], rl[4];
                ldmx4(rh, bd);
                ldmx4(rl, bd + 10240);
                const int j0 = jp * 2, j1 = jp * 2 + 1;
#pragma unroll
                for (int t = 0; t < 4; t++) {
                    mma_bf16(acc[t][j0], afh[t], rh + 0);
                    mma_bf16(acc[t][j1], afh[t], rh + 2);
                }
#pragma unroll
                for (int t = 0; t < 4; t++) {
                    mma_bf16(acc[t][j0], afh[t], rl + 0);
                    mma_bf16(acc[t][j1], afh[t], rl + 2);
                }
#pragma unroll
                for (int t = 0; t < 4; t++) {
                    mma_bf16(acc[t][j0], afl[t], rh + 0);
                    mma_bf16(acc[t][j1], afl[t], rh + 2);
                }
            }
        }
        __syncthreads();
    }
#undef ISSUE

    // ---------------- epilogue ----------------
    const int rbase = warp_m * 64 + (lane >> 2);
    const int cbase = warp_n * 64 + (lane & 3) * 2;

    if (EPI == 0) {
        float* C = (float*)O0 + (size_t)z * batchC;
#pragma unroll
        for (int t = 0; t < 4; t++)
#pragma unroll
            for (int j = 0; j < 8; j++) {
                int rr = m0 + rbase + t * 16;
                int cc = n0 + cbase + j * 8;
                *(float2*)(C + (size_t)rr * ldC + cc) =
                    make_float2(acc[t][j][0], acc[t][j][1]);
                *(float2*)(C + (size_t)(rr + 8) * ldC + cc) =
                    make_float2(acc[t][j][2], acc[t][j][3]);
            }
    } else if (EPI == 1) {
        bf16* Oh = (bf16*)O0;
        bf16* Ol = (bf16*)O1;
#pragma unroll
        for (int t = 0; t < 4; t++)
#pragma unroll
            for (int j = 0; j < 8; j++)
#pragma unroll
                for (int h = 0; h < 2; h++) {
                    int rr = m0 + rbase + t * 16 + h * 8;
                    int cc = n0 + cbase + j * 8;
                    float x0 = acc[t][j][h * 2 + 0], x1 = acc[t][j][h * 2 + 1];
                    bf16 h0 = __float2bfloat16(x0), h1 = __float2bfloat16(x1);
                    bf16 l0 = __float2bfloat16(x0 - __bfloat162float(h0));
                    bf16 l1 = __float2bfloat16(x1 - __bfloat162float(h1));
                    __nv_bfloat162 hp; hp.x = h0; hp.y = h1;
                    __nv_bfloat162 lp; lp.x = l0; lp.y = l1;
                    *(__nv_bfloat162*)(Oh + (size_t)rr * ldC + cc) = hp;
                    *(__nv_bfloat162*)(Ol + (size_t)rr * ldC + cc) = lp;
                }
    } else {
        // EPI 2: V -> V^T.  Stage full 128x128 fp32 tile, then transposed store
        float* st = (float*)smem;
#pragma unroll
        for (int t = 0; t < 4; t++)
#pragma unroll
            for (int j = 0; j < 8; j++)
#pragma unroll
                for (int h = 0; h < 2; h++) {
                    int rr = rbase + t * 16 + h * 8;
                    int cc = cbase + j * 8;
                    st[(size_t)rr * 129 + cc + 0] = acc[t][j][h * 2 + 0];
                    st[(size_t)rr * 129 + cc + 1] = acc[t][j][h * 2 + 1];
                }
        __syncthreads();
        bf16* Oh = (bf16*)O0;
        bf16* Ol = (bf16*)O1;
        for (int idx = tid; idx < 128 * 128; idx += 128) {
            int nl = idx >> 7, ml = idx & 127;
            int mg = m0 + ml;
            int b = mg >> 11, mloc = mg & 2047;
            float x = st[(size_t)ml * 129 + nl];
            bf16 h = __float2bfloat16(x);
            bf16 l = __float2bfloat16(x - __bfloat162float(h));
            size_t o = (size_t)b * DIM * SEQ + (size_t)(n0 + nl) * SEQ + mloc;
            Oh[o] = h;
            Ol[o] = l;
        }
    }
}

// ---------------- prep kernels ----------------------------------------------
__global__ void split_kernel(const float* __restrict__ X,
                             bf16* __restrict__ H, bf16* __restrict__ L, int n)
{
    int i = blockIdx.x * 256 + threadIdx.x;
    if (i < n) {
        float x = X[i];
        bf16 h = __float2bfloat16(x);
        H[i] = h;
        L[i] = __float2bfloat16(x - __bfloat162float(h));
    }
}

__global__ void wsplit_kernel(const float* __restrict__ W,
                              bf16* __restrict__ TH, bf16* __restrict__ TL)
{
    int i = blockIdx.x * 256 + threadIdx.x;   // out idx f*DIM + d
    int f = i / DIM, d = i % DIM;
    float x = W[d * DIM + f];
    bf16 h = __float2bfloat16(x);
    TH[i] = h;
    TL[i] = __float2bfloat16(x - __bfloat162float(h));
}

// ---------------- softmax: S fp32 -> P split bf16 ---------------------------
__global__ void __launch_bounds__(256)
softmax_kernel(const float* __restrict__ S,
               bf16* __restrict__ Ph, bf16* __restrict__ Pl)
{
    const int row = blockIdx.x;
    const float* p = S + (size_t)row * SEQ;
    const int tid = threadIdx.x;

    float v[8];
    float m = -1e30f;
#pragma unroll
    for (int i = 0; i < 8; i++) {
        v[i] = p[tid + i * 256];
        m = fmaxf(m, v[i]);
    }

    __shared__ float red[256];
    red[tid] = m;
    __syncthreads();
#pragma unroll
    for (int s = 128; s > 0; s >>= 1) {
        if (tid < s) red[tid] = fmaxf(red[tid], red[tid + s]);
        __syncthreads();
    }
    m = red[0];
    __syncthreads();

    float sum = 0.0f;
#pragma unroll
    for (int i = 0; i < 8; i++) {
        v[i] = expf(v[i] - m);
        sum += v[i];
    }
    red[tid] = sum;
    __syncthreads();
#pragma unroll
    for (int s = 128; s > 0; s >>= 1) {
        if (tid < s) red[tid] += red[tid + s];
        __syncthreads();
    }
    const float inv = 1.0f / red[0];
#pragma unroll
    for (int i = 0; i < 8; i++) {
        float pr = v[i] * inv;
        bf16 h = __float2bfloat16(pr);
        size_t o = (size_t)row * SEQ + tid + i * 256;
        Ph[o] = h;
        Pl[o] = __float2bfloat16(pr - __bfloat162float(h));
    }
}

// ---------------------------------------------------------------------------
extern "C" void kernel_launch(void* const* d_in, const int* in_sizes, int n_in,
                              void* d_out, int out_size)
{
    const float* X  = (const float*)d_in[0];
    const float* Wq = (const float*)d_in[1];
    const float* Wk = (const float*)d_in[2];
    const float* Wv = (const float*)d_in[3];
    float* out = (float*)d_out;

    bf16 *xh, *xl, *wth, *wtl, *qh, *ql, *kh, *kl, *vth, *vtl, *ph, *pl;
    float* s;
    cudaGetSymbolAddress((void**)&xh, g_xh);
    cudaGetSymbolAddress((void**)&xl, g_xl);
    cudaGetSymbolAddress((void**)&wth, g_wth);
    cudaGetSymbolAddress((void**)&wtl, g_wtl);
    cudaGetSymbolAddress((void**)&qh, g_qh);
    cudaGetSymbolAddress((void**)&ql, g_ql);
    cudaGetSymbolAddress((void**)&kh, g_kh);
    cudaGetSymbolAddress((void**)&kl, g_kl);
    cudaGetSymbolAddress((void**)&vth, g_vth);
    cudaGetSymbolAddress((void**)&vtl, g_vtl);
    cudaGetSymbolAddress((void**)&ph, g_ph);
    cudaGetSymbolAddress((void**)&pl, g_pl);
    cudaGetSymbolAddress((void**)&s, g_s);

    cudaFuncSetAttribute(gemm_mma<0>, cudaFuncAttributeMaxDynamicSharedMemorySize, SMEMSZ);
    cudaFuncSetAttribute(gemm_mma<1>, cudaFuncAttributeMaxDynamicSharedMemorySize, SMEMSZ);
    cudaFuncSetAttribute(gemm_mma<2>, cudaFuncAttributeMaxDynamicSharedMemorySize, SMEMSZ);

    const int nx = MTOT * DIM;
    split_kernel<<<nx / 256, 256>>>(X, xh, xl, nx);
    wsplit_kernel<<<(DIM * DIM) / 256, 256>>>(Wq, wth + 0 * DIM * DIM, wtl + 0 * DIM * DIM);
    wsplit_kernel<<<(DIM * DIM) / 256, 256>>>(Wk, wth + 1 * DIM * DIM, wtl + 1 * DIM * DIM);
    wsplit_kernel<<<(DIM * DIM) / 256, 256>>>(Wv, wth + 2 * DIM * DIM, wtl + 2 * DIM * DIM);

    // Projections: [16384,768] = X * (W^T)^T
    dim3 gp(DIM / 128, MTOT / 128, 1);
    gemm_mma<1><<<gp, 128, SMEMSZ>>>(xh, xl, wth + 0 * DIM * DIM, wtl + 0 * DIM * DIM,
                                     qh, ql, DIM, 0, 0, 0, DIM);
    gemm_mma<1><<<gp, 128, SMEMSZ>>>(xh, xl, wth + 1 * DIM * DIM, wtl + 1 * DIM * DIM,
                                     kh, kl, DIM, 0, 0, 0, DIM);
    gemm_mma<2><<<gp, 128, SMEMSZ>>>(xh, xl, wth + 2 * DIM * DIM, wtl + 2 * DIM * DIM,
                                     vth, vtl, DIM, 0, 0, 0, 0);

    // Scores: per batch S = Q * K^T, [2048,2048], K=768
    dim3 gs(SEQ / 128, SEQ / 128, BSZ);
    gemm_mma<0><<<gs, 128, SMEMSZ>>>(qh, ql, kh, kl, s, nullptr, DIM,
                                     (long)SEQ * DIM, (long)SEQ * DIM,
                                     (long)SEQ * SEQ, SEQ);

    softmax_kernel<<<BSZ * SEQ, 256>>>(s, ph, pl);

    // Out: per batch O = P * (V^T)^T, [2048,768], K=2048
    dim3 go(DIM / 128, SEQ / 128, BSZ);
    gemm_mma<0><<<go, 128, SMEMSZ>>>(ph, pl, vth, vtl, out, nullptr, SEQ,
                                     (long)SEQ * SEQ, (long)DIM * SEQ,
                                     (long)SEQ * DIM, DIM);
}

// round 7
// speedup vs baseline: 1.1811x; 1.0738x over previous
#include <cuda_runtime.h>
#include <cuda_fp16.h>
#include <cstdint>

typedef __half f16;

constexpr int BSZ = 8, SEQ = 2048, DIM = 768;
constexpr int MTOT = BSZ * SEQ;            // 16384

// CTA tile 128x128, BK=32. Padded 80B rows (64B data + 16B pad) for ldmatrix.
constexpr int ROWB   = 80;
constexpr int A_HI   = 0;                  // 128 x 80 = 10240 per tile
constexpr int A_LO   = 10240;
constexpr int B_HI   = 20480;
constexpr int B_LO   = 30720;              // only for 3-pass kernels
constexpr int SMEMSZ3 = 2 * 40960;        // 2-stage x 4 tiles = 81920
constexpr int SMEMSZ2 = 3 * 30720;        // 3-stage x 3 tiles = 92160 (PV)
// epi2 staging needs 128*129*4 = 66048 <= both

// ---------------- static device scratch (allocation-free rule) --------------
__device__ f16 g_xh[(size_t)MTOT * DIM];
__device__ f16 g_xl[(size_t)MTOT * DIM];
__device__ f16 g_wth[3][DIM * DIM];
__device__ f16 g_wtl[3][DIM * DIM];
__device__ f16 g_qh[(size_t)MTOT * DIM];
__device__ f16 g_ql[(size_t)MTOT * DIM];
__device__ f16 g_kh[(size_t)MTOT * DIM];
__device__ f16 g_kl[(size_t)MTOT * DIM];
__device__ f16 g_vth[(size_t)MTOT * DIM];   // V^T per batch: [b][768][2048], hi only
__device__ float g_s[(size_t)BSZ * SEQ * SEQ];
__device__ f16 g_ph[(size_t)BSZ * SEQ * SEQ];
__device__ f16 g_pl[(size_t)BSZ * SEQ * SEQ];

// ---------------- PTX helpers ----------------------------------------------
__device__ __forceinline__ uint32_t smem_u32(const void* p) {
    uint32_t a;
    asm("{ .reg .u64 t; cvta.to.shared.u64 t, %1; cvt.u32.u64 %0, t; }"
        : "=r"(a) : "l"(p));
    return a;
}

__device__ __forceinline__ void ldmx4(uint32_t* r, uint32_t a) {
    asm volatile("ldmatrix.sync.aligned.m8n8.x4.shared.b16 {%0,%1,%2,%3}, [%4];"
                 : "=r"(r[0]), "=r"(r[1]), "=r"(r[2]), "=r"(r[3]) : "r"(a));
}

__device__ __forceinline__ void mma_f16(float* c, const uint32_t* a, const uint32_t* b) {
    asm volatile(
        "mma.sync.aligned.m16n8k16.row.col.f32.f16.f16.f32 "
        "{%0,%1,%2,%3}, {%4,%5,%6,%7}, {%8,%9}, {%0,%1,%2,%3};"
        : "+f"(c[0]), "+f"(c[1]), "+f"(c[2]), "+f"(c[3])
        : "r"(a[0]), "r"(a[1]), "r"(a[2]), "r"(a[3]), "r"(b[0]), "r"(b[1]));
}

__device__ __forceinline__ void cpasync16(uint32_t s, const void* g) {
    asm volatile("cp.async.cg.shared.global [%0], [%1], 16;" :: "r"(s), "l"(g));
}

// ---------------------------------------------------------------------------
// HMMA GEMM: C[M,N] = A * B^T in split-fp16, fp32 accum.
// NPASS=3: AhBh + AhBl + AlBh (4 tiles, 2-stage pipeline).
// NPASS=2: AhBh + AlBh        (3 tiles, no Bl, 3-stage pipeline) — PV path.
// CTA tile 128x128xBK32, 128 threads, warp grid 2(M) x 2(N), warp tile 64x64.
// One __syncthreads per mainloop iteration.
// EPI 0: fp32 C (batched).  EPI 1: f16 hi/lo C.  EPI 2: f16 hi + V->V^T.
// ---------------------------------------------------------------------------
template <int EPI, int NPASS>
__global__ void __launch_bounds__(128, 2)
gemm_mma(const f16* __restrict__ Ah, const f16* __restrict__ Al,
         const f16* __restrict__ Bh, const f16* __restrict__ Bl,
         void* __restrict__ O0, void* __restrict__ O1,
         int K, long batchA, long batchB, long batchC, int ldC)
{
    constexpr int NSTAGE = (NPASS == 2) ? 3 : 2;
    constexpr int STB    = (NPASS == 2) ? 30720 : 40960;

    extern __shared__ char smem[];
    const int tid = threadIdx.x, lane = tid & 31, wid = tid >> 5;
    const int z = blockIdx.z;
    const int m0 = blockIdx.y * 128, n0 = blockIdx.x * 128;
    const int warp_m = wid & 1, warp_n = wid >> 1;

    const char* pAh = (const char*)(Ah + (size_t)z * batchA);
    const char* pAl = (const char*)(Al + (size_t)z * batchA);
    const char* pBh = (const char*)(Bh + (size_t)z * batchB);
    const char* pBl = (NPASS == 3) ? (const char*)(Bl + (size_t)z * batchB) : nullptr;

    const uint32_t sb = smem_u32(smem);
    const uint32_t rowbytes = (uint32_t)K * 2;

    float acc[4][8][4];
#pragma unroll
    for (int t = 0; t < 4; t++)
#pragma unroll
        for (int j = 0; j < 8; j++)
#pragma unroll
            for (int c = 0; c < 4; c++) acc[t][j][c] = 0.0f;

    const int nch = K >> 5;

#define ISSUE(kc, buf)                                                           \
    {                                                                            \
        uint32_t s0 = sb + (buf) * STB;                                          \
        uint32_t kcb = (uint32_t)(kc) * 64;                                      \
        _Pragma("unroll")                                                        \
        for (int i = 0; i < 4; i++) {                                            \
            int c = tid + i * 128;                                               \
            int r = c >> 2, sg = (c & 3) * 16;                                   \
            size_t goA = (size_t)(m0 + r) * rowbytes + kcb + sg;                 \
            size_t goB = (size_t)(n0 + r) * rowbytes + kcb + sg;                 \
            uint32_t so = r * ROWB + sg;                                         \
            cpasync16(s0 + A_HI + so, pAh + goA);                                \
            cpasync16(s0 + A_LO + so, pAl + goA);                                \
            cpasync16(s0 + B_HI + so, pBh + goB);                                \
            if (NPASS == 3) cpasync16(s0 + B_LO + so, pBl + goB);                \
        }                                                                        \
        asm volatile("cp.async.commit_group;" ::: "memory");                     \
    }

    ISSUE(0, 0);
    if (NSTAGE == 3) ISSUE(1, 1);

    int cb = 0;                      // compute buffer
    int ib = NSTAGE - 1;             // next issue buffer
    for (int kc = 0; kc < nch; kc++) {
        if (NSTAGE == 3) asm volatile("cp.async.wait_group 1;" ::: "memory");
        else             asm volatile("cp.async.wait_group 0;" ::: "memory");
        __syncthreads();             // stage cb ready; stage ib's readers done

        const int knext = kc + NSTAGE - 1;
        if (knext < nch) ISSUE(knext, ib);
        ib = (ib + 1 == NSTAGE) ? 0 : ib + 1;

        const uint32_t sA = sb + cb * STB;
        cb = (cb + 1 == NSTAGE) ? 0 : cb + 1;

#pragma unroll
        for (int ks = 0; ks < 2; ks++) {
            const uint32_t kb = ks * 32;   // byte offset of k16 slice
            uint32_t afh[4][4], afl[4][4];

            const uint32_t aoff = (warp_m * 64 + (lane & 15)) * ROWB + kb + (lane >> 4) * 16;
#pragma unroll
            for (int t = 0; t < 4; t++) {
                uint32_t ad = sA + aoff + t * 16 * ROWB;
                ldmx4(afh[t], ad);
                ldmx4(afl[t], ad + 10240);
            }

            const uint32_t boff = (warp_n * 64 + (lane >> 4) * 8 + (lane & 7)) * ROWB +
                                  kb + ((lane >> 3) & 1) * 16;
#pragma unroll
            for (int jp = 0; jp < 4; jp++) {
                uint32_t bd = sA + B_HI + boff + jp * 16 * ROWB;
                uint32_t rh[4];
                ldmx4(rh, bd);
                const int j0 = jp * 2, j1 = jp * 2 + 1;
#pragma unroll
                for (int t = 0; t < 4; t++) {
                    mma_f16(acc[t][j0], afh[t], rh + 0);
                    mma_f16(acc[t][j1], afh[t], rh + 2);
                }
                if (NPASS == 3) {
                    uint32_t rl[4];
                    ldmx4(rl, bd + 10240);
#pragma unroll
                    for (int t = 0; t < 4; t++) {
                        mma_f16(acc[t][j0], afh[t], rl + 0);
                        mma_f16(acc[t][j1], afh[t], rl + 2);
                    }
                }
#pragma unroll
                for (int t = 0; t < 4; t++) {
                    mma_f16(acc[t][j0], afl[t], rh + 0);
                    mma_f16(acc[t][j1], afl[t], rh + 2);
                }
            }
        }
    }
#undef ISSUE

    __syncthreads();   // protect smem before epilogue staging reuse

    // ---------------- epilogue ----------------
    const int rbase = warp_m * 64 + (lane >> 2);
    const int cbase = warp_n * 64 + (lane & 3) * 2;

    if (EPI == 0) {
        float* C = (float*)O0 + (size_t)z * batchC;
#pragma unroll
        for (int t = 0; t < 4; t++)
#pragma unroll
            for (int j = 0; j < 8; j++) {
                int rr = m0 + rbase + t * 16;
                int cc = n0 + cbase + j * 8;
                *(float2*)(C + (size_t)rr * ldC + cc) =
                    make_float2(acc[t][j][0], acc[t][j][1]);
                *(float2*)(C + (size_t)(rr + 8) * ldC + cc) =
                    make_float2(acc[t][j][2], acc[t][j][3]);
            }
    } else if (EPI == 1) {
        f16* Oh = (f16*)O0;
        f16* Ol = (f16*)O1;
#pragma unroll
        for (int t = 0; t < 4; t++)
#pragma unroll
            for (int j = 0; j < 8; j++)
#pragma unroll
                for (int h = 0; h < 2; h++) {
                    int rr = m0 + rbase + t * 16 + h * 8;
                    int cc = n0 + cbase + j * 8;
                    float x0 = acc[t][j][h * 2 + 0], x1 = acc[t][j][h * 2 + 1];
                    f16 h0 = __float2half(x0), h1 = __float2half(x1);
                    f16 l0 = __float2half(x0 - __half2float(h0));
                    f16 l1 = __float2half(x1 - __half2float(h1));
                    *(__half2*)(Oh + (size_t)rr * ldC + cc) = __halves2half2(h0, h1);
                    *(__half2*)(Ol + (size_t)rr * ldC + cc) = __halves2half2(l0, l1);
                }
    } else {
        // EPI 2: V -> V^T (hi only). Stage 128x128 fp32 tile, transposed store.
        float* st = (float*)smem;
#pragma unroll
        for (int t = 0; t < 4; t++)
#pragma unroll
            for (int j = 0; j < 8; j++)
#pragma unroll
                for (int h = 0; h < 2; h++) {
                    int rr = rbase + t * 16 + h * 8;
                    int cc = cbase + j * 8;
                    st[(size_t)rr * 129 + cc + 0] = acc[t][j][h * 2 + 0];
                    st[(size_t)rr * 129 + cc + 1] = acc[t][j][h * 2 + 1];
                }
        __syncthreads();
        f16* Oh = (f16*)O0;
        for (int idx = tid; idx < 128 * 128; idx += 128) {
            int nl = idx >> 7, ml = idx & 127;
            int mg = m0 + ml;
            int b = mg >> 11, mloc = mg & 2047;
            float x = st[(size_t)ml * 129 + nl];
            size_t o = (size_t)b * DIM * SEQ + (size_t)(n0 + nl) * SEQ + mloc;
            Oh[o] = __float2half(x);
        }
    }
}

// ---------------- prep kernels ----------------------------------------------
__global__ void split_kernel(const float* __restrict__ X,
                             f16* __restrict__ H, f16* __restrict__ L, int n)
{
    int i = blockIdx.x * 256 + threadIdx.x;
    if (i < n) {
        float x = X[i];
        f16 h = __float2half(x);
        H[i] = h;
        L[i] = __float2half(x - __half2float(h));
    }
}

__global__ void wsplit_kernel(const float* __restrict__ W,
                              f16* __restrict__ TH, f16* __restrict__ TL)
{
    int i = blockIdx.x * 256 + threadIdx.x;   // out idx f*DIM + d
    int f = i / DIM, d = i % DIM;
    float x = W[d * DIM + f];
    f16 h = __float2half(x);
    TH[i] = h;
    TL[i] = __float2half(x - __half2float(h));
}

// ---------------- softmax: S fp32 -> P split fp16 ---------------------------
__global__ void __launch_bounds__(256)
softmax_kernel(const float* __restrict__ S,
               f16* __restrict__ Ph, f16* __restrict__ Pl)
{
    const int row = blockIdx.x;
    const float* p = S + (size_t)row * SEQ;
    const int tid = threadIdx.x;

    float v[8];
    float m = -1e30f;
#pragma unroll
    for (int i = 0; i < 8; i++) {
        v[i] = p[tid + i * 256];
        m = fmaxf(m, v[i]);
    }

    __shared__ float red[256];
    red[tid] = m;
    __syncthreads();
#pragma unroll
    for (int s = 128; s > 0; s >>= 1) {
        if (tid < s) red[tid] = fmaxf(red[tid], red[tid + s]);
        __syncthreads();
    }
    m = red[0];
    __syncthreads();

    float sum = 0.0f;
#pragma unroll
    for (int i = 0; i < 8; i++) {
        v[i] = expf(v[i] - m);
        sum += v[i];
    }
    red[tid] = sum;
    __syncthreads();
#pragma unroll
    for (int s = 128; s > 0; s >>= 1) {
        if (tid < s) red[tid] += red[tid + s];
        __syncthreads();
    }
    const float inv = 1.0f / red[0];
#pragma unroll
    for (int i = 0; i < 8; i++) {
        float pr = v[i] * inv;
        f16 h = __float2half(pr);
        size_t o = (size_t)row * SEQ + tid + i * 256;
        Ph[o] = h;
        Pl[o] = __float2half(pr - __half2float(h));
    }
}

// ---------------------------------------------------------------------------
extern "C" void kernel_launch(void* const* d_in, const int* in_sizes, int n_in,
                              void* d_out, int out_size)
{
    const float* X  = (const float*)d_in[0];
    const float* Wq = (const float*)d_in[1];
    const float* Wk = (const float*)d_in[2];
    const float* Wv = (const float*)d_in[3];
    float* out = (float*)d_out;

    f16 *xh, *xl, *wth, *wtl, *qh, *ql, *kh, *kl, *vth, *ph, *pl;
    float* s;
    cudaGetSymbolAddress((void**)&xh, g_xh);
    cudaGetSymbolAddress((void**)&xl, g_xl);
    cudaGetSymbolAddress((void**)&wth, g_wth);
    cudaGetSymbolAddress((void**)&wtl, g_wtl);
    cudaGetSymbolAddress((void**)&qh, g_qh);
    cudaGetSymbolAddress((void**)&ql, g_ql);
    cudaGetSymbolAddress((void**)&kh, g_kh);
    cudaGetSymbolAddress((void**)&kl, g_kl);
    cudaGetSymbolAddress((void**)&vth, g_vth);
    cudaGetSymbolAddress((void**)&ph, g_ph);
    cudaGetSymbolAddress((void**)&pl, g_pl);
    cudaGetSymbolAddress((void**)&s, g_s);

    cudaFuncSetAttribute(gemm_mma<0, 3>, cudaFuncAttributeMaxDynamicSharedMemorySize, SMEMSZ3);
    cudaFuncSetAttribute(gemm_mma<0, 2>, cudaFuncAttributeMaxDynamicSharedMemorySize, SMEMSZ2);
    cudaFuncSetAttribute(gemm_mma<1, 3>, cudaFuncAttributeMaxDynamicSharedMemorySize, SMEMSZ3);
    cudaFuncSetAttribute(gemm_mma<2, 3>, cudaFuncAttributeMaxDynamicSharedMemorySize, SMEMSZ3);

    const int nx = MTOT * DIM;
    split_kernel<<<nx / 256, 256>>>(X, xh, xl, nx);
    wsplit_kernel<<<(DIM * DIM) / 256, 256>>>(Wq, wth + 0 * DIM * DIM, wtl + 0 * DIM * DIM);
    wsplit_kernel<<<(DIM * DIM) / 256, 256>>>(Wk, wth + 1 * DIM * DIM, wtl + 1 * DIM * DIM);
    wsplit_kernel<<<(DIM * DIM) / 256, 256>>>(Wv, wth + 2 * DIM * DIM, wtl + 2 * DIM * DIM);

    // Projections: [16384,768] = X * (W^T)^T  (3-pass)
    dim3 gp(DIM / 128, MTOT / 128, 1);
    gemm_mma<1, 3><<<gp, 128, SMEMSZ3>>>(xh, xl, wth + 0 * DIM * DIM, wtl + 0 * DIM * DIM,
                                         qh, ql, DIM, 0, 0, 0, DIM);
    gemm_mma<1, 3><<<gp, 128, SMEMSZ3>>>(xh, xl, wth + 1 * DIM * DIM, wtl + 1 * DIM * DIM,
                                         kh, kl, DIM, 0, 0, 0, DIM);
    gemm_mma<2, 3><<<gp, 128, SMEMSZ3>>>(xh, xl, wth + 2 * DIM * DIM, wtl + 2 * DIM * DIM,
                                         vth, nullptr, DIM, 0, 0, 0, 0);

    // Scores: per batch S = Q * K^T, [2048,2048], K=768 (3-pass)
    dim3 gs(SEQ / 128, SEQ / 128, BSZ);
    gemm_mma<0, 3><<<gs, 128, SMEMSZ3>>>(qh, ql, kh, kl, s, nullptr, DIM,
                                         (long)SEQ * DIM, (long)SEQ * DIM,
                                         (long)SEQ * SEQ, SEQ);

    softmax_kernel<<<BSZ * SEQ, 256>>>(s, ph, pl);

    // Out: per batch O = P * (V^T)^T, [2048,768], K=2048 (2-pass, V hi only)
    dim3 go(DIM / 128, SEQ / 128, BSZ);
    gemm_mma<0, 2><<<go, 128, SMEMSZ2>>>(ph, pl, vth, nullptr, out, nullptr, SEQ,
                                         (long)SEQ * SEQ, (long)DIM * SEQ,
                                         (long)SEQ * DIM, DIM);
}

// round 8
// speedup vs baseline: 1.2579x; 1.0650x over previous
#include <cuda_runtime.h>
#include <cuda_fp16.h>
#include <cstdint>

typedef __half f16;

constexpr int BSZ = 8, SEQ = 2048, DIM = 768;
constexpr int MTOT = BSZ * SEQ;            // 16384

// CTA tile 128x128, BK=32. Padded 80B rows (64B data + 16B pad) for ldmatrix.
constexpr int ROWB   = 80;
constexpr int A_HI   = 0;                  // 128 x 80 = 10240 per tile
constexpr int A_LO   = 10240;
constexpr int B_HI   = 20480;
constexpr int B_LO   = 30720;              // 3-pass kernels only
constexpr int SMEMSZ3 = 2 * 40960;        // 2-stage x 4 tiles = 81920
constexpr int SMEMSZ2 = 3 * 30720;        // 3-stage x 3 tiles = 92160 (PV)
// epi2 staging needs 128*129*4 = 66048 <= both

// ---------------- static device scratch (allocation-free rule) --------------
__device__ f16 g_xh[(size_t)MTOT * DIM];
__device__ f16 g_xl[(size_t)MTOT * DIM];
__device__ f16 g_wth[3][DIM * DIM];        // contiguous [2304 x 768] B^T
__device__ f16 g_wtl[3][DIM * DIM];
__device__ f16 g_qh[(size_t)MTOT * DIM];
__device__ f16 g_ql[(size_t)MTOT * DIM];
__device__ f16 g_kh[(size_t)MTOT * DIM];
__device__ f16 g_kl[(size_t)MTOT * DIM];
__device__ f16 g_vth[(size_t)MTOT * DIM];   // V^T per batch: [b][768][2048], hi only
__device__ float g_s[(size_t)BSZ * SEQ * SEQ];
__device__ f16 g_ph[(size_t)BSZ * SEQ * SEQ];
__device__ f16 g_pl[(size_t)BSZ * SEQ * SEQ];

// ---------------- PTX helpers ----------------------------------------------
__device__ __forceinline__ uint32_t smem_u32(const void* p) {
    uint32_t a;
    asm("{ .reg .u64 t; cvta.to.shared.u64 t, %1; cvt.u32.u64 %0, t; }"
        : "=r"(a) : "l"(p));
    return a;
}

__device__ __forceinline__ void ldmx4(uint32_t* r, uint32_t a) {
    asm volatile("ldmatrix.sync.aligned.m8n8.x4.shared.b16 {%0,%1,%2,%3}, [%4];"
                 : "=r"(r[0]), "=r"(r[1]), "=r"(r[2]), "=r"(r[3]) : "r"(a));
}

__device__ __forceinline__ void mma_f16(float* c, const uint32_t* a, const uint32_t* b) {
    asm volatile(
        "mma.sync.aligned.m16n8k16.row.col.f32.f16.f16.f32 "
        "{%0,%1,%2,%3}, {%4,%5,%6,%7}, {%8,%9}, {%0,%1,%2,%3};"
        : "+f"(c[0]), "+f"(c[1]), "+f"(c[2]), "+f"(c[3])
        : "r"(a[0]), "r"(a[1]), "r"(a[2]), "r"(a[3]), "r"(b[0]), "r"(b[1]));
}

__device__ __forceinline__ void cpasync16(uint32_t s, const void* g) {
    asm volatile("cp.async.cg.shared.global [%0], [%1], 16;" :: "r"(s), "l"(g));
}

// ---------------------------------------------------------------------------
// Fused QKV projection: A = X [16384,768] split-fp16; B^T = [Wq|Wk|Wv]^T
// [2304,768] split-fp16.  Grid (18, 128); n0 selects output + pass count:
//   n0 <  768 : Q hi/lo (3-pass)
//   n0 < 1536 : K hi/lo (3-pass)
//   else      : V^T hi  (2-pass; drops XhWvl, ~2.8e-4 rel on V)
// ---------------------------------------------------------------------------
__global__ void __launch_bounds__(128, 2)
proj_fused(const f16* __restrict__ Ah, const f16* __restrict__ Al,
           const f16* __restrict__ Bh, const f16* __restrict__ Bl,
           f16* __restrict__ Qh, f16* __restrict__ Ql,
           f16* __restrict__ Kh, f16* __restrict__ Kl,
           f16* __restrict__ Vt)
{
    extern __shared__ char smem[];
    const int tid = threadIdx.x, lane = tid & 31, wid = tid >> 5;
    const int m0 = blockIdx.y * 128, n0 = blockIdx.x * 128;
    const int warp_m = wid & 1, warp_n = wid >> 1;
    const bool three = (n0 < 1536);

    const char* pAh = (const char*)Ah;
    const char* pAl = (const char*)Al;
    const char* pBh = (const char*)Bh;
    const char* pBl = (const char*)Bl;

    const uint32_t sb = smem_u32(smem);
    const uint32_t rowbytes = DIM * 2;     // 1536

    float acc[4][8][4];
#pragma unroll
    for (int t = 0; t < 4; t++)
#pragma unroll
        for (int j = 0; j < 8; j++)
#pragma unroll
            for (int c = 0; c < 4; c++) acc[t][j][c] = 0.0f;

#define PISSUE(kc, buf)                                                          \
    {                                                                            \
        uint32_t s0 = sb + (buf) * 40960;                                        \
        uint32_t kcb = (uint32_t)(kc) * 64;                                      \
        _Pragma("unroll")                                                        \
        for (int i = 0; i < 4; i++) {                                            \
            int c = tid + i * 128;                                               \
            int r = c >> 2, sg = (c & 3) * 16;                                   \
            size_t goA = (size_t)(m0 + r) * rowbytes + kcb + sg;                 \
            size_t goB = (size_t)(n0 + r) * rowbytes + kcb + sg;                 \
            uint32_t so = r * ROWB + sg;                                         \
            cpasync16(s0 + A_HI + so, pAh + goA);                                \
            cpasync16(s0 + A_LO + so, pAl + goA);                                \
            cpasync16(s0 + B_HI + so, pBh + goB);                                \
            if (three) cpasync16(s0 + B_LO + so, pBl + goB);                     \
        }                                                                        \
        asm volatile("cp.async.commit_group;" ::: "memory");                     \
    }

    PISSUE(0, 0);

    const int nch = DIM >> 5;   // 24
    for (int kc = 0; kc < nch; kc++) {
        asm volatile("cp.async.wait_group 0;" ::: "memory");
        __syncthreads();

        if (kc + 1 < nch) PISSUE(kc + 1, (kc + 1) & 1);

        const uint32_t sA = sb + (kc & 1) * 40960;
#pragma unroll
        for (int ks = 0; ks < 2; ks++) {
            const uint32_t kb = ks * 32;
            uint32_t afh[4][4], afl[4][4];

            const uint32_t aoff = (warp_m * 64 + (lane & 15)) * ROWB + kb + (lane >> 4) * 16;
#pragma unroll
            for (int t = 0; t < 4; t++) {
                uint32_t ad = sA + aoff + t * 16 * ROWB;
                ldmx4(afh[t], ad);
                ldmx4(afl[t], ad + 10240);
            }

            const uint32_t boff = (warp_n * 64 + (lane >> 4) * 8 + (lane & 7)) * ROWB +
                                  kb + ((lane >> 3) & 1) * 16;
#pragma unroll
            for (int jp = 0; jp < 4; jp++) {
                uint32_t bd = sA + B_HI + boff + jp * 16 * ROWB;
                uint32_t rh[4];
                ldmx4(rh, bd);
                const int j0 = jp * 2, j1 = jp * 2 + 1;
#pragma unroll
                for (int t = 0; t < 4; t++) {
                    mma_f16(acc[t][j0], afh[t], rh + 0);
                    mma_f16(acc[t][j1], afh[t], rh + 2);
                }
                if (three) {
                    uint32_t rl[4];
                    ldmx4(rl, bd + 10240);
#pragma unroll
                    for (int t = 0; t < 4; t++) {
                        mma_f16(acc[t][j0], afh[t], rl + 0);
                        mma_f16(acc[t][j1], afh[t], rl + 2);
                    }
                }
#pragma unroll
                for (int t = 0; t < 4; t++) {
                    mma_f16(acc[t][j0], afl[t], rh + 0);
                    mma_f16(acc[t][j1], afl[t], rh + 2);
                }
            }
        }
        __syncthreads();
    }
#undef PISSUE

    // ---------------- epilogue dispatch ----------------
    const int rbase = warp_m * 64 + (lane >> 2);
    const int cbase = warp_n * 64 + (lane & 3) * 2;

    if (three) {
        f16* Oh = (n0 < 768) ? Qh : Kh;
        f16* Ol = (n0 < 768) ? Ql : Kl;
        const int nc0 = (n0 < 768) ? n0 : n0 - 768;
#pragma unroll
        for (int t = 0; t < 4; t++)
#pragma unroll
            for (int j = 0; j < 8; j++)
#pragma unroll
                for (int h = 0; h < 2; h++) {
                    int rr = m0 + rbase + t * 16 + h * 8;
                    int cc = nc0 + cbase + j * 8;
                    float x0 = acc[t][j][h * 2 + 0], x1 = acc[t][j][h * 2 + 1];
                    f16 h0 = __float2half(x0), h1 = __float2half(x1);
                    f16 l0 = __float2half(x0 - __half2float(h0));
                    f16 l1 = __float2half(x1 - __half2float(h1));
                    *(__half2*)(Oh + (size_t)rr * DIM + cc) = __halves2half2(h0, h1);
                    *(__half2*)(Ol + (size_t)rr * DIM + cc) = __halves2half2(l0, l1);
                }
    } else {
        // V^T: stage 128x128 fp32 tile in smem, store transposed (hi only)
        float* st = (float*)smem;
#pragma unroll
        for (int t = 0; t < 4; t++)
#pragma unroll
            for (int j = 0; j < 8; j++)
#pragma unroll
                for (int h = 0; h < 2; h++) {
                    int rr = rbase + t * 16 + h * 8;
                    int cc = cbase + j * 8;
                    st[(size_t)rr * 129 + cc + 0] = acc[t][j][h * 2 + 0];
                    st[(size_t)rr * 129 + cc + 1] = acc[t][j][h * 2 + 1];
                }
        __syncthreads();
        const int nv0 = n0 - 1536;
        for (int idx = tid; idx < 128 * 128; idx += 128) {
            int nl = idx >> 7, ml = idx & 127;
            int mg = m0 + ml;
            int b = mg >> 11, mloc = mg & 2047;
            float x = st[(size_t)ml * 129 + nl];
            size_t o = (size_t)b * DIM * SEQ + (size_t)(nv0 + nl) * SEQ + mloc;
            Vt[o] = __float2half(x);
        }
    }
}

// ---------------------------------------------------------------------------
// Batched GEMM for scores (NPASS=3, fp32 out) and PV (NPASS=2, fp32 out).
// CTA tile 128x128xBK32, 128 threads, warp tile 64x64.
// ---------------------------------------------------------------------------
template <int NPASS>
__global__ void __launch_bounds__(128, 2)
gemm_mma(const f16* __restrict__ Ah, const f16* __restrict__ Al,
         const f16* __restrict__ Bh, const f16* __restrict__ Bl,
         float* __restrict__ O,
         int K, long batchA, long batchB, long batchC, int ldC)
{
    constexpr int NSTAGE = (NPASS == 2) ? 3 : 2;
    constexpr int STB    = (NPASS == 2) ? 30720 : 40960;

    extern __shared__ char smem[];
    const int tid = threadIdx.x, lane = tid & 31, wid = tid >> 5;
    const int z = blockIdx.z;
    const int m0 = blockIdx.y * 128, n0 = blockIdx.x * 128;
    const int warp_m = wid & 1, warp_n = wid >> 1;

    const char* pAh = (const char*)(Ah + (size_t)z * batchA);
    const char* pAl = (const char*)(Al + (size_t)z * batchA);
    const char* pBh = (const char*)(Bh + (size_t)z * batchB);
    const char* pBl = (NPASS == 3) ? (const char*)(Bl + (size_t)z * batchB) : nullptr;

    const uint32_t sb = smem_u32(smem);
    const uint32_t rowbytes = (uint32_t)K * 2;

    float acc[4][8][4];
#pragma unroll
    for (int t = 0; t < 4; t++)
#pragma unroll
        for (int j = 0; j < 8; j++)
#pragma unroll
            for (int c = 0; c < 4; c++) acc[t][j][c] = 0.0f;

    const int nch = K >> 5;

#define ISSUE(kc, buf)                                                           \
    {                                                                            \
        uint32_t s0 = sb + (buf) * STB;                                          \
        uint32_t kcb = (uint32_t)(kc) * 64;                                      \
        _Pragma("unroll")                                                        \
        for (int i = 0; i < 4; i++) {                                            \
            int c = tid + i * 128;                                               \
            int r = c >> 2, sg = (c & 3) * 16;                                   \
            size_t goA = (size_t)(m0 + r) * rowbytes + kcb + sg;                 \
            size_t goB = (size_t)(n0 + r) * rowbytes + kcb + sg;                 \
            uint32_t so = r * ROWB + sg;                                         \
            cpasync16(s0 + A_HI + so, pAh + goA);                                \
            cpasync16(s0 + A_LO + so, pAl + goA);                                \
            cpasync16(s0 + B_HI + so, pBh + goB);                                \
            if (NPASS == 3) cpasync16(s0 + B_LO + so, pBl + goB);                \
        }                                                                        \
        asm volatile("cp.async.commit_group;" ::: "memory");                     \
    }

    ISSUE(0, 0);
    if (NSTAGE == 3) ISSUE(1, 1);

    int cb = 0;
    int ib = NSTAGE - 1;
    for (int kc = 0; kc < nch; kc++) {
        if (NSTAGE == 3) asm volatile("cp.async.wait_group 1;" ::: "memory");
        else             asm volatile("cp.async.wait_group 0;" ::: "memory");
        __syncthreads();

        const int knext = kc + NSTAGE - 1;
        if (knext < nch) ISSUE(knext, ib);
        ib = (ib + 1 == NSTAGE) ? 0 : ib + 1;

        const uint32_t sA = sb + cb * STB;
        cb = (cb + 1 == NSTAGE) ? 0 : cb + 1;

#pragma unroll
        for (int ks = 0; ks < 2; ks++) {
            const uint32_t kb = ks * 32;
            uint32_t afh[4][4], afl[4][4];

            const uint32_t aoff = (warp_m * 64 + (lane & 15)) * ROWB + kb + (lane >> 4) * 16;
#pragma unroll
            for (int t = 0; t < 4; t++) {
                uint32_t ad = sA + aoff + t * 16 * ROWB;
                ldmx4(afh[t], ad);
                ldmx4(afl[t], ad + 10240);
            }

            const uint32_t boff = (warp_n * 64 + (lane >> 4) * 8 + (lane & 7)) * ROWB +
                                  kb + ((lane >> 3) & 1) * 16;
#pragma unroll
            for (int jp = 0; jp < 4; jp++) {
                uint32_t bd = sA + B_HI + boff + jp * 16 * ROWB;
                uint32_t rh[4];
                ldmx4(rh, bd);
                const int j0 = jp * 2, j1 = jp * 2 + 1;
#pragma unroll
                for (int t = 0; t < 4; t++) {
                    mma_f16(acc[t][j0], afh[t], rh + 0);
                    mma_f16(acc[t][j1], afh[t], rh + 2);
                }
                if (NPASS == 3) {
                    uint32_t rl[4];
                    ldmx4(rl, bd + 10240);
#pragma unroll
                    for (int t = 0; t < 4; t++) {
                        mma_f16(acc[t][j0], afh[t], rl + 0);
                        mma_f16(acc[t][j1], afh[t], rl + 2);
                    }
                }
#pragma unroll
                for (int t = 0; t < 4; t++) {
                    mma_f16(acc[t][j0], afl[t], rh + 0);
                    mma_f16(acc[t][j1], afl[t], rh + 2);
                }
            }
        }
    }
#undef ISSUE

    // fp32 epilogue
    const int rbase = warp_m * 64 + (lane >> 2);
    const int cbase = warp_n * 64 + (lane & 3) * 2;
    float* C = O + (size_t)z * batchC;
#pragma unroll
    for (int t = 0; t < 4; t++)
#pragma unroll
        for (int j = 0; j < 8; j++) {
            int rr = m0 + rbase + t * 16;
            int cc = n0 + cbase + j * 8;
            *(float2*)(C + (size_t)rr * ldC + cc) =
                make_float2(acc[t][j][0], acc[t][j][1]);
            *(float2*)(C + (size_t)(rr + 8) * ldC + cc) =
                make_float2(acc[t][j][2], acc[t][j][3]);
        }
}

// ---------------- prep kernels ----------------------------------------------
__global__ void split_kernel(const float* __restrict__ X,
                             f16* __restrict__ H, f16* __restrict__ L, int n)
{
    int i = blockIdx.x * 256 + threadIdx.x;
    if (i < n) {
        float x = X[i];
        f16 h = __float2half(x);
        H[i] = h;
        L[i] = __float2half(x - __half2float(h));
    }
}

__global__ void wsplit_kernel(const float* __restrict__ W,
                              f16* __restrict__ TH, f16* __restrict__ TL)
{
    int i = blockIdx.x * 256 + threadIdx.x;   // out idx f*DIM + d
    int f = i / DIM, d = i % DIM;
    float x = W[d * DIM + f];
    f16 h = __float2half(x);
    TH[i] = h;
    TL[i] = __float2half(x - __half2float(h));
}

// ---------------- softmax: S fp32 -> P split fp16 (vectorized) --------------
__global__ void __launch_bounds__(256)
softmax_kernel(const float* __restrict__ S,
               f16* __restrict__ Ph, f16* __restrict__ Pl)
{
    const int row = blockIdx.x;
    const float4* p4 = (const float4*)(S + (size_t)row * SEQ);
    const int tid = threadIdx.x;

    float4 va = p4[tid];
    float4 vb = p4[tid + 256];
    float m = fmaxf(fmaxf(fmaxf(va.x, va.y), fmaxf(va.z, va.w)),
                    fmaxf(fmaxf(vb.x, vb.y), fmaxf(vb.z, vb.w)));

    __shared__ float red[256];
    red[tid] = m;
    __syncthreads();
#pragma unroll
    for (int s = 128; s > 0; s >>= 1) {
        if (tid < s) red[tid] = fmaxf(red[tid], red[tid + s]);
        __syncthreads();
    }
    m = red[0];
    __syncthreads();

    va.x = expf(va.x - m); va.y = expf(va.y - m);
    va.z = expf(va.z - m); va.w = expf(va.w - m);
    vb.x = expf(vb.x - m); vb.y = expf(vb.y - m);
    vb.z = expf(vb.z - m); vb.w = expf(vb.w - m);
    float sum = (va.x + va.y) + (va.z + va.w) + (vb.x + vb.y) + (vb.z + vb.w);

    red[tid] = sum;
    __syncthreads();
#pragma unroll
    for (int s = 128; s > 0; s >>= 1) {
        if (tid < s) red[tid] += red[tid + s];
        __syncthreads();
    }
    const float inv = 1.0f / red[0];

    __half2* ph2 = (__half2*)(Ph + (size_t)row * SEQ);
    __half2* pl2 = (__half2*)(Pl + (size_t)row * SEQ);
#pragma unroll
    for (int half = 0; half < 2; half++) {
        float4 v = half ? vb : va;
        int base = (half ? (tid + 256) : tid) * 2;   // half2 index
        float p0 = v.x * inv, p1 = v.y * inv, p2 = v.z * inv, p3 = v.w * inv;
        f16 h0 = __float2half(p0), h1 = __float2half(p1);
        f16 h2 = __float2half(p2), h3 = __float2half(p3);
        ph2[base + 0] = __halves2half2(h0, h1);
        ph2[base + 1] = __halves2half2(h2, h3);
        pl2[base + 0] = __halves2half2(__float2half(p0 - __half2float(h0)),
                                       __float2half(p1 - __half2float(h1)));
        pl2[base + 1] = __halves2half2(__float2half(p2 - __half2float(h2)),
                                       __float2half(p3 - __half2float(h3)));
    }
}

// ---------------------------------------------------------------------------
extern "C" void kernel_launch(void* const* d_in, const int* in_sizes, int n_in,
                              void* d_out, int out_size)
{
    const float* X  = (const float*)d_in[0];
    const float* Wq = (const float*)d_in[1];
    const float* Wk = (const float*)d_in[2];
    const float* Wv = (const float*)d_in[3];
    float* out = (float*)d_out;

    f16 *xh, *xl, *wth, *wtl, *qh, *ql, *kh, *kl, *vth, *ph, *pl;
    float* s;
    cudaGetSymbolAddress((void**)&xh, g_xh);
    cudaGetSymbolAddress((void**)&xl, g_xl);
    cudaGetSymbolAddress((void**)&wth, g_wth);
    cudaGetSymbolAddress((void**)&wtl, g_wtl);
    cudaGetSymbolAddress((void**)&qh, g_qh);
    cudaGetSymbolAddress((void**)&ql, g_ql);
    cudaGetSymbolAddress((void**)&kh, g_kh);
    cudaGetSymbolAddress((void**)&kl, g_kl);
    cudaGetSymbolAddress((void**)&vth, g_vth);
    cudaGetSymbolAddress((void**)&ph, g_ph);
    cudaGetSymbolAddress((void**)&pl, g_pl);
    cudaGetSymbolAddress((void**)&s, g_s);

    cudaFuncSetAttribute(proj_fused, cudaFuncAttributeMaxDynamicSharedMemorySize, SMEMSZ3);
    cudaFuncSetAttribute(gemm_mma<3>, cudaFuncAttributeMaxDynamicSharedMemorySize, SMEMSZ3);
    cudaFuncSetAttribute(gemm_mma<2>, cudaFuncAttributeMaxDynamicSharedMemorySize, SMEMSZ2);

    const int nx = MTOT * DIM;
    split_kernel<<<nx / 256, 256>>>(X, xh, xl, nx);
    wsplit_kernel<<<(DIM * DIM) / 256, 256>>>(Wq, wth + 0 * DIM * DIM, wtl + 0 * DIM * DIM);
    wsplit_kernel<<<(DIM * DIM) / 256, 256>>>(Wk, wth + 1 * DIM * DIM, wtl + 1 * DIM * DIM);
    wsplit_kernel<<<(DIM * DIM) / 256, 256>>>(Wv, wth + 2 * DIM * DIM, wtl + 2 * DIM * DIM);

    // Fused QKV projection: grid 18 x 128 (2304 CTAs, ~7.8 waves)
    dim3 gp(3 * DIM / 128, MTOT / 128, 1);
    proj_fused<<<gp, 128, SMEMSZ3>>>(xh, xl, wth, wtl, qh, ql, kh, kl, vth);

    // Scores: per batch S = Q * K^T, [2048,2048], K=768 (3-pass)
    dim3 gs(SEQ / 128, SEQ / 128, BSZ);
    gemm_mma<3><<<gs, 128, SMEMSZ3>>>(qh, ql, kh, kl, s, DIM,
                                      (long)SEQ * DIM, (long)SEQ * DIM,
                                      (long)SEQ * SEQ, SEQ);

    softmax_kernel<<<BSZ * SEQ, 256>>>(s, ph, pl);

    // Out: per batch O = P * (V^T)^T, [2048,768], K=2048 (2-pass, V hi only)
    dim3 go(DIM / 128, SEQ / 128, BSZ);
    gemm_mma<2><<<go, 128, SMEMSZ2>>>(ph, pl, vth, nullptr, out, SEQ,
                                      (long)SEQ * SEQ, (long)DIM * SEQ,
                                      (long)SEQ * DIM, DIM);
}

// round 9
// speedup vs baseline: 1.4589x; 1.1599x over previous
#include <cuda_runtime.h>
#include <cuda_fp16.h>
#include <cstdint>

typedef __half f16;

constexpr int BSZ = 8, SEQ = 2048, DIM = 768;
constexpr int MTOT = BSZ * SEQ;            // 16384

// Swizzled smem tiles: 128 rows x 64B, chunk ^= (row>>1)&3  (16B chunks).
constexpr int TILE  = 8192;
constexpr int A_HI  = 0;
constexpr int A_LO  = TILE;
constexpr int B_HI  = 2 * TILE;
constexpr int B_LO  = 3 * TILE;            // 3-pass only
constexpr int STB3  = 4 * TILE;            // 32768
constexpr int STB2  = 3 * TILE;            // 24576
constexpr int SMEMSZ3 = 3 * STB3;          // 98304 (3-stage)
constexpr int SMEMSZ2 = 4 * STB2;          // 98304 (4-stage)
// epi2 staging needs 128*129*4 = 66048 <= both

// ---------------- static device scratch (allocation-free rule) --------------
__device__ f16 g_xh[(size_t)MTOT * DIM];
__device__ f16 g_xl[(size_t)MTOT * DIM];
__device__ f16 g_wth[3][DIM * DIM];        // contiguous [2304 x 768] B^T
__device__ f16 g_wtl[3][DIM * DIM];
__device__ f16 g_qh[(size_t)MTOT * DIM];
__device__ f16 g_ql[(size_t)MTOT * DIM];
__device__ f16 g_kh[(size_t)MTOT * DIM];
__device__ f16 g_kl[(size_t)MTOT * DIM];
__device__ f16 g_vth[(size_t)MTOT * DIM];   // V^T per batch: [b][768][2048], hi only
__device__ float g_s[(size_t)BSZ * SEQ * SEQ];
__device__ f16 g_ph[(size_t)BSZ * SEQ * SEQ];
__device__ f16 g_pl[(size_t)BSZ * SEQ * SEQ];

// ---------------- PTX helpers ----------------------------------------------
__device__ __forceinline__ uint32_t smem_u32(const void* p) {
    uint32_t a;
    asm("{ .reg .u64 t; cvta.to.shared.u64 t, %1; cvt.u32.u64 %0, t; }"
        : "=r"(a) : "l"(p));
    return a;
}

__device__ __forceinline__ void ldmx4(uint32_t* r, uint32_t a) {
    asm volatile("ldmatrix.sync.aligned.m8n8.x4.shared.b16 {%0,%1,%2,%3}, [%4];"
                 : "=r"(r[0]), "=r"(r[1]), "=r"(r[2]), "=r"(r[3]) : "r"(a));
}

__device__ __forceinline__ void mma_f16(float* c, const uint32_t* a, const uint32_t* b) {
    asm volatile(
        "mma.sync.aligned.m16n8k16.row.col.f32.f16.f16.f32 "
        "{%0,%1,%2,%3}, {%4,%5,%6,%7}, {%8,%9}, {%0,%1,%2,%3};"
        : "+f"(c[0]), "+f"(c[1]), "+f"(c[2]), "+f"(c[3])
        : "r"(a[0]), "r"(a[1]), "r"(a[2]), "r"(a[3]), "r"(b[0]), "r"(b[1]));
}

__device__ __forceinline__ void cpasync16(uint32_t s, const void* g) {
    asm volatile("cp.async.cg.shared.global [%0], [%1], 16;" :: "r"(s), "l"(g));
}

// swizzled in-tile offset for (row, 16B-chunk)
__device__ __forceinline__ uint32_t swz(int row, int ch) {
    return (uint32_t)(row * 64 + ((ch ^ ((row >> 1) & 3)) << 4));
}

// ---------------------------------------------------------------------------
// Fused QKV projection.  Grid (18, 128); n0 selects output + pass count:
//   n0 <  768 : Q hi/lo (3-pass)   n0 < 1536 : K hi/lo (3-pass)
//   else      : V^T hi  (2-pass)
// 3-stage cp.async pipeline, swizzled smem.
// ---------------------------------------------------------------------------
__global__ void __launch_bounds__(128, 2)
proj_fused(const f16* __restrict__ Ah, const f16* __restrict__ Al,
           const f16* __restrict__ Bh, const f16* __restrict__ Bl,
           f16* __restrict__ Qh, f16* __restrict__ Ql,
           f16* __restrict__ Kh, f16* __restrict__ Kl,
           f16* __restrict__ Vt)
{
    extern __shared__ char smem[];
    const int tid = threadIdx.x, lane = tid & 31, wid = tid >> 5;
    const int m0 = blockIdx.y * 128, n0 = blockIdx.x * 128;
    const int warp_m = wid & 1, warp_n = wid >> 1;
    const bool three = (n0 < 1536);

    const char* pAh = (const char*)Ah;
    const char* pAl = (const char*)Al;
    const char* pBh = (const char*)Bh;
    const char* pBl = (const char*)Bl;

    const uint32_t sb = smem_u32(smem);
    const uint32_t rowbytes = DIM * 2;

    float acc[4][8][4];
#pragma unroll
    for (int t = 0; t < 4; t++)
#pragma unroll
        for (int j = 0; j < 8; j++)
#pragma unroll
            for (int c = 0; c < 4; c++) acc[t][j][c] = 0.0f;

#define PISSUE(kc, buf)                                                          \
    {                                                                            \
        uint32_t s0 = sb + (buf) * STB3;                                         \
        uint32_t kcb = (uint32_t)(kc) * 64;                                      \
        _Pragma("unroll")                                                        \
        for (int i = 0; i < 4; i++) {                                            \
            int c = tid + i * 128;                                               \
            int r = c >> 2, ch = c & 3;                                          \
            size_t goA = (size_t)(m0 + r) * rowbytes + kcb + ch * 16;            \
            size_t goB = (size_t)(n0 + r) * rowbytes + kcb + ch * 16;            \
            uint32_t so = swz(r, ch);                                            \
            cpasync16(s0 + A_HI + so, pAh + goA);                                \
            cpasync16(s0 + A_LO + so, pAl + goA);                                \
            cpasync16(s0 + B_HI + so, pBh + goB);                                \
            if (three) cpasync16(s0 + B_LO + so, pBl + goB);                     \
        }                                                                        \
        asm volatile("cp.async.commit_group;" ::: "memory");                     \
    }

    PISSUE(0, 0);
    PISSUE(1, 1);

    const int nch = DIM >> 5;   // 24
    int cb = 0, ib = 2;
    for (int kc = 0; kc < nch; kc++) {
        asm volatile("cp.async.wait_group 1;" ::: "memory");
        __syncthreads();

        const int knext = kc + 2;
        if (knext < nch) PISSUE(knext, ib);
        ib = (ib + 1 == 3) ? 0 : ib + 1;

        const uint32_t sA = sb + cb * STB3;
        cb = (cb + 1 == 3) ? 0 : cb + 1;

#pragma unroll
        for (int ks = 0; ks < 2; ks++) {
            uint32_t afh[4][4], afl[4][4];

            const int ra0 = warp_m * 64 + (lane & 15);
            const int ca = ks * 2 + (lane >> 4);
#pragma unroll
            for (int t = 0; t < 4; t++) {
                uint32_t ad = sA + swz(ra0 + t * 16, ca);
                ldmx4(afh[t], ad);
                ldmx4(afl[t], ad + TILE);
            }

            const int rb0 = warp_n * 64 + (lane >> 4) * 8 + (lane & 7);
            const int cbk = ks * 2 + ((lane >> 3) & 1);
#pragma unroll
            for (int jp = 0; jp < 4; jp++) {
                uint32_t bd = sA + B_HI + swz(rb0 + jp * 16, cbk);
                uint32_t rh[4];
                ldmx4(rh, bd);
                const int j0 = jp * 2, j1 = jp * 2 + 1;
#pragma unroll
                for (int t = 0; t < 4; t++) {
                    mma_f16(acc[t][j0], afh[t], rh + 0);
                    mma_f16(acc[t][j1], afh[t], rh + 2);
                }
                if (three) {
                    uint32_t rl[4];
                    ldmx4(rl, bd + TILE);
#pragma unroll
                    for (int t = 0; t < 4; t++) {
                        mma_f16(acc[t][j0], afh[t], rl + 0);
                        mma_f16(acc[t][j1], afh[t], rl + 2);
                    }
                }
#pragma unroll
                for (int t = 0; t < 4; t++) {
                    mma_f16(acc[t][j0], afl[t], rh + 0);
                    mma_f16(acc[t][j1], afl[t], rh + 2);
                }
            }
        }
        __syncthreads();
    }
#undef PISSUE

    // ---------------- epilogue dispatch ----------------
    const int rbase = warp_m * 64 + (lane >> 2);
    const int cbase = warp_n * 64 + (lane & 3) * 2;

    if (three) {
        f16* Oh = (n0 < 768) ? Qh : Kh;
        f16* Ol = (n0 < 768) ? Ql : Kl;
        const int nc0 = (n0 < 768) ? n0 : n0 - 768;
#pragma unroll
        for (int t = 0; t < 4; t++)
#pragma unroll
            for (int j = 0; j < 8; j++)
#pragma unroll
                for (int h = 0; h < 2; h++) {
                    int rr = m0 + rbase + t * 16 + h * 8;
                    int cc = nc0 + cbase + j * 8;
                    float x0 = acc[t][j][h * 2 + 0], x1 = acc[t][j][h * 2 + 1];
                    f16 h0 = __float2half(x0), h1 = __float2half(x1);
                    f16 l0 = __float2half(x0 - __half2float(h0));
                    f16 l1 = __float2half(x1 - __half2float(h1));
                    *(__half2*)(Oh + (size_t)rr * DIM + cc) = __halves2half2(h0, h1);
                    *(__half2*)(Ol + (size_t)rr * DIM + cc) = __halves2half2(l0, l1);
                }
    } else {
        float* st = (float*)smem;
#pragma unroll
        for (int t = 0; t < 4; t++)
#pragma unroll
            for (int j = 0; j < 8; j++)
#pragma unroll
                for (int h = 0; h < 2; h++) {
                    int rr = rbase + t * 16 + h * 8;
                    int cc = cbase + j * 8;
                    st[(size_t)rr * 129 + cc + 0] = acc[t][j][h * 2 + 0];
                    st[(size_t)rr * 129 + cc + 1] = acc[t][j][h * 2 + 1];
                }
        __syncthreads();
        const int nv0 = n0 - 1536;
        for (int idx = tid; idx < 128 * 128; idx += 128) {
            int nl = idx >> 7, ml = idx & 127;
            int mg = m0 + ml;
            int b = mg >> 11, mloc = mg & 2047;
            float x = st[(size_t)ml * 129 + nl];
            size_t o = (size_t)b * DIM * SEQ + (size_t)(nv0 + nl) * SEQ + mloc;
            Vt[o] = __float2half(x);
        }
    }
}

// ---------------------------------------------------------------------------
// Batched GEMM: scores (NPASS=3, 3-stage) and PV (NPASS=2, 4-stage), fp32 out.
// ---------------------------------------------------------------------------
template <int NPASS>
__global__ void __launch_bounds__(128, 2)
gemm_mma(const f16* __restrict__ Ah, const f16* __restrict__ Al,
         const f16* __restrict__ Bh, const f16* __restrict__ Bl,
         float* __restrict__ O,
         int K, long batchA, long batchB, long batchC, int ldC)
{
    constexpr int NSTAGE = (NPASS == 2) ? 4 : 3;
    constexpr int STB    = (NPASS == 2) ? STB2 : STB3;

    extern __shared__ char smem[];
    const int tid = threadIdx.x, lane = tid & 31, wid = tid >> 5;
    const int z = blockIdx.z;
    const int m0 = blockIdx.y * 128, n0 = blockIdx.x * 128;
    const int warp_m = wid & 1, warp_n = wid >> 1;

    const char* pAh = (const char*)(Ah + (size_t)z * batchA);
    const char* pAl = (const char*)(Al + (size_t)z * batchA);
    const char* pBh = (const char*)(Bh + (size_t)z * batchB);
    const char* pBl = (NPASS == 3) ? (const char*)(Bl + (size_t)z * batchB) : nullptr;

    const uint32_t sb = smem_u32(smem);
    const uint32_t rowbytes = (uint32_t)K * 2;

    float acc[4][8][4];
#pragma unroll
    for (int t = 0; t < 4; t++)
#pragma unroll
        for (int j = 0; j < 8; j++)
#pragma unroll
            for (int c = 0; c < 4; c++) acc[t][j][c] = 0.0f;

    const int nch = K >> 5;

#define ISSUE(kc, buf)                                                           \
    {                                                                            \
        uint32_t s0 = sb + (buf) * STB;                                          \
        uint32_t kcb = (uint32_t)(kc) * 64;                                      \
        _Pragma("unroll")                                                        \
        for (int i = 0; i < 4; i++) {                                            \
            int c = tid + i * 128;                                               \
            int r = c >> 2, ch = c & 3;                                          \
            size_t goA = (size_t)(m0 + r) * rowbytes + kcb + ch * 16;            \
            size_t goB = (size_t)(n0 + r) * rowbytes + kcb + ch * 16;            \
            uint32_t so = swz(r, ch);                                            \
            cpasync16(s0 + A_HI + so, pAh + goA);                                \
            cpasync16(s0 + A_LO + so, pAl + goA);                                \
            cpasync16(s0 + B_HI + so, pBh + goB);                                \
            if (NPASS == 3) cpasync16(s0 + B_LO + so, pBl + goB);                \
        }                                                                        \
        asm volatile("cp.async.commit_group;" ::: "memory");                     \
    }

#pragma unroll
    for (int p = 0; p < NSTAGE - 1; p++) ISSUE(p, p);

    int cb = 0, ib = NSTAGE - 1;
    for (int kc = 0; kc < nch; kc++) {
        asm volatile("cp.async.wait_group %0;" :: "n"(NSTAGE - 2) : "memory");
        __syncthreads();

        const int knext = kc + NSTAGE - 1;
        if (knext < nch) ISSUE(knext, ib);
        ib = (ib + 1 == NSTAGE) ? 0 : ib + 1;

        const uint32_t sA = sb + cb * STB;
        cb = (cb + 1 == NSTAGE) ? 0 : cb + 1;

#pragma unroll
        for (int ks = 0; ks < 2; ks++) {
            uint32_t afh[4][4], afl[4][4];

            const int ra0 = warp_m * 64 + (lane & 15);
            const int ca = ks * 2 + (lane >> 4);
#pragma unroll
            for (int t = 0; t < 4; t++) {
                uint32_t ad = sA + swz(ra0 + t * 16, ca);
                ldmx4(afh[t], ad);
                ldmx4(afl[t], ad + TILE);
            }

            const int rb0 = warp_n * 64 + (lane >> 4) * 8 + (lane & 7);
            const int cbk = ks * 2 + ((lane >> 3) & 1);
#pragma unroll
            for (int jp = 0; jp < 4; jp++) {
                uint32_t bd = sA + B_HI + swz(rb0 + jp * 16, cbk);
                uint32_t rh[4];
                ldmx4(rh, bd);
                const int j0 = jp * 2, j1 = jp * 2 + 1;
#pragma unroll
                for (int t = 0; t < 4; t++) {
                    mma_f16(acc[t][j0], afh[t], rh + 0);
                    mma_f16(acc[t][j1], afh[t], rh + 2);
                }
                if (NPASS == 3) {
                    uint32_t rl[4];
                    ldmx4(rl, bd + TILE);
#pragma unroll
                    for (int t = 0; t < 4; t++) {
                        mma_f16(acc[t][j0], afh[t], rl + 0);
                        mma_f16(acc[t][j1], afh[t], rl + 2);
                    }
                }
#pragma unroll
                for (int t = 0; t < 4; t++) {
                    mma_f16(acc[t][j0], afl[t], rh + 0);
                    mma_f16(acc[t][j1], afl[t], rh + 2);
                }
            }
        }
        __syncthreads();
    }
#undef ISSUE

    // fp32 epilogue
    const int rbase = warp_m * 64 + (lane >> 2);
    const int cbase = warp_n * 64 + (lane & 3) * 2;
    float* C = O + (size_t)z * batchC;
#pragma unroll
    for (int t = 0; t < 4; t++)
#pragma unroll
        for (int j = 0; j < 8; j++) {
            int rr = m0 + rbase + t * 16;
            int cc = n0 + cbase + j * 8;
            *(float2*)(C + (size_t)rr * ldC + cc) =
                make_float2(acc[t][j][0], acc[t][j][1]);
            *(float2*)(C + (size_t)(rr + 8) * ldC + cc) =
                make_float2(acc[t][j][2], acc[t][j][3]);
        }
}

// ---------------- prep kernels ----------------------------------------------
__global__ void split_kernel(const float* __restrict__ X,
                             f16* __restrict__ H, f16* __restrict__ L, int n)
{
    int i = blockIdx.x * 256 + threadIdx.x;
    if (i < n) {
        float x = X[i];
        f16 h = __float2half(x);
        H[i] = h;
        L[i] = __float2half(x - __half2float(h));
    }
}

__global__ void wsplit_kernel(const float* __restrict__ W,
                              f16* __restrict__ TH, f16* __restrict__ TL)
{
    int i = blockIdx.x * 256 + threadIdx.x;   // out idx f*DIM + d
    int f = i / DIM, d = i % DIM;
    float x = W[d * DIM + f];
    f16 h = __float2half(x);
    TH[i] = h;
    TL[i] = __float2half(x - __half2float(h));
}

// ---------------- softmax: S fp32 -> P split fp16 (vectorized) --------------
__global__ void __launch_bounds__(256)
softmax_kernel(const float* __restrict__ S,
               f16* __restrict__ Ph, f16* __restrict__ Pl)
{
    const int row = blockIdx.x;
    const float4* p4 = (const float4*)(S + (size_t)row * SEQ);
    const int tid = threadIdx.x;

    float4 va = p4[tid];
    float4 vb = p4[tid + 256];
    float m = fmaxf(fmaxf(fmaxf(va.x, va.y), fmaxf(va.z, va.w)),
                    fmaxf(fmaxf(vb.x, vb.y), fmaxf(vb.z, vb.w)));

    __shared__ float red[256];
    red[tid] = m;
    __syncthreads();
#pragma unroll
    for (int s = 128; s > 0; s >>= 1) {
        if (tid < s) red[tid] = fmaxf(red[tid], red[tid + s]);
        __syncthreads();
    }
    m = red[0];
    __syncthreads();

    va.x = expf(va.x - m); va.y = expf(va.y - m);
    va.z = expf(va.z - m); va.w = expf(va.w - m);
    vb.x = expf(vb.x - m); vb.y = expf(vb.y - m);
    vb.z = expf(vb.z - m); vb.w = expf(vb.w - m);
    float sum = (va.x + va.y) + (va.z + va.w) + (vb.x + vb.y) + (vb.z + vb.w);

    red[tid] = sum;
    __syncthreads();
#pragma unroll
    for (int s = 128; s > 0; s >>= 1) {
        if (tid < s) red[tid] += red[tid + s];
        __syncthreads();
    }
    const float inv = 1.0f / red[0];

    __half2* ph2 = (__half2*)(Ph + (size_t)row * SEQ);
    __half2* pl2 = (__half2*)(Pl + (size_t)row * SEQ);
#pragma unroll
    for (int half = 0; half < 2; half++) {
        float4 v = half ? vb : va;
        int base = (half ? (tid + 256) : tid) * 2;
        float p0 = v.x * inv, p1 = v.y * inv, p2 = v.z * inv, p3 = v.w * inv;
        f16 h0 = __float2half(p0), h1 = __float2half(p1);
        f16 h2 = __float2half(p2), h3 = __float2half(p3);
        ph2[base + 0] = __halves2half2(h0, h1);
        ph2[base + 1] = __halves2half2(h2, h3);
        pl2[base + 0] = __halves2half2(__float2half(p0 - __half2float(h0)),
                                       __float2half(p1 - __half2float(h1)));
        pl2[base + 1] = __halves2half2(__float2half(p2 - __half2float(h2)),
                                       __float2half(p3 - __half2float(h3)));
    }
}

// ---------------------------------------------------------------------------
extern "C" void kernel_launch(void* const* d_in, const int* in_sizes, int n_in,
                              void* d_out, int out_size)
{
    const float* X  = (const float*)d_in[0];
    const float* Wq = (const float*)d_in[1];
    const float* Wk = (const float*)d_in[2];
    const float* Wv = (const float*)d_in[3];
    float* out = (float*)d_out;

    f16 *xh, *xl, *wth, *wtl, *qh, *ql, *kh, *kl, *vth, *ph, *pl;
    float* s;
    cudaGetSymbolAddress((void**)&xh, g_xh);
    cudaGetSymbolAddress((void**)&xl, g_xl);
    cudaGetSymbolAddress((void**)&wth, g_wth);
    cudaGetSymbolAddress((void**)&wtl, g_wtl);
    cudaGetSymbolAddress((void**)&qh, g_qh);
    cudaGetSymbolAddress((void**)&ql, g_ql);
    cudaGetSymbolAddress((void**)&kh, g_kh);
    cudaGetSymbolAddress((void**)&kl, g_kl);
    cudaGetSymbolAddress((void**)&vth, g_vth);
    cudaGetSymbolAddress((void**)&ph, g_ph);
    cudaGetSymbolAddress((void**)&pl, g_pl);
    cudaGetSymbolAddress((void**)&s, g_s);

    cudaFuncSetAttribute(proj_fused, cudaFuncAttributeMaxDynamicSharedMemorySize, SMEMSZ3);
    cudaFuncSetAttribute(gemm_mma<3>, cudaFuncAttributeMaxDynamicSharedMemorySize, SMEMSZ3);
    cudaFuncSetAttribute(gemm_mma<2>, cudaFuncAttributeMaxDynamicSharedMemorySize, SMEMSZ2);

    const int nx = MTOT * DIM;
    split_kernel<<<nx / 256, 256>>>(X, xh, xl, nx);
    wsplit_kernel<<<(DIM * DIM) / 256, 256>>>(Wq, wth + 0 * DIM * DIM, wtl + 0 * DIM * DIM);
    wsplit_kernel<<<(DIM * DIM) / 256, 256>>>(Wk, wth + 1 * DIM * DIM, wtl + 1 * DIM * DIM);
    wsplit_kernel<<<(DIM * DIM) / 256, 256>>>(Wv, wth + 2 * DIM * DIM, wtl + 2 * DIM * DIM);

    // Fused QKV projection: grid 18 x 128
    dim3 gp(3 * DIM / 128, MTOT / 128, 1);
    proj_fused<<<gp, 128, SMEMSZ3>>>(xh, xl, wth, wtl, qh, ql, kh, kl, vth);

    // Scores: per batch S = Q * K^T, [2048,2048], K=768 (3-pass, 3-stage)
    dim3 gs(SEQ / 128, SEQ / 128, BSZ);
    gemm_mma<3><<<gs, 128, SMEMSZ3>>>(qh, ql, kh, kl, s, DIM,
                                      (long)SEQ * DIM, (long)SEQ * DIM,
                                      (long)SEQ * SEQ, SEQ);

    softmax_kernel<<<BSZ * SEQ, 256>>>(s, ph, pl);

    // Out: per batch O = P * (V^T)^T, [2048,768], K=2048 (2-pass, 4-stage)
    dim3 go(DIM / 128, SEQ / 128, BSZ);
    gemm_mma<2><<<go, 128, SMEMSZ2>>>(ph, pl, vth, nullptr, out, SEQ,
                                      (long)SEQ * SEQ, (long)DIM * SEQ,
                                      (long)SEQ * DIM, DIM);
}

// round 10
// speedup vs baseline: 1.6845x; 1.1546x over previous
#include <cuda_runtime.h>
#include <cuda_fp16.h>
#include <cstdint>

typedef __half f16;

constexpr int BSZ = 8, SEQ = 2048, DIM = 768;
constexpr int MTOT = BSZ * SEQ;            // 16384

// Swizzled smem tiles: 128 rows x 64B, chunk ^= (row>>1)&3  (16B chunks).
constexpr int TILE  = 8192;
constexpr int STB3  = 4 * TILE;            // 32768: Ah,Al,Bh,Bl
constexpr int STB1  = 2 * TILE;            // 16384: Ah,Bh (PV)
constexpr int SMEMSZ3 = 3 * STB3;          // 98304 (3-stage)
constexpr int SMEMSZ1 = 5 * STB1;          // 81920 (5-stage, PV)
// epi2 staging needs 128*129*4 = 66048 <= both

// ---------------- static device scratch (allocation-free rule) --------------
__device__ f16 g_xh[(size_t)MTOT * DIM];
__device__ f16 g_xl[(size_t)MTOT * DIM];
__device__ f16 g_wth[3][DIM * DIM];        // contiguous [2304 x 768] B^T
__device__ f16 g_wtl[3][DIM * DIM];
__device__ f16 g_qh[(size_t)MTOT * DIM];
__device__ f16 g_ql[(size_t)MTOT * DIM];
__device__ f16 g_kh[(size_t)MTOT * DIM];
__device__ f16 g_kl[(size_t)MTOT * DIM];
__device__ f16 g_vth[(size_t)MTOT * DIM];   // V^T per batch: [b][768][2048], hi only
__device__ float g_s[(size_t)BSZ * SEQ * SEQ];
__device__ f16 g_ph[(size_t)BSZ * SEQ * SEQ];

// ---------------- PTX helpers ----------------------------------------------
__device__ __forceinline__ uint32_t smem_u32(const void* p) {
    uint32_t a;
    asm("{ .reg .u64 t; cvta.to.shared.u64 t, %1; cvt.u32.u64 %0, t; }"
        : "=r"(a) : "l"(p));
    return a;
}

__device__ __forceinline__ void ldmx4(uint32_t* r, uint32_t a) {
    asm volatile("ldmatrix.sync.aligned.m8n8.x4.shared.b16 {%0,%1,%2,%3}, [%4];"
                 : "=r"(r[0]), "=r"(r[1]), "=r"(r[2]), "=r"(r[3]) : "r"(a));
}

__device__ __forceinline__ void mma_f16(float* c, const uint32_t* a, const uint32_t* b) {
    asm volatile(
        "mma.sync.aligned.m16n8k16.row.col.f32.f16.f16.f32 "
        "{%0,%1,%2,%3}, {%4,%5,%6,%7}, {%8,%9}, {%0,%1,%2,%3};"
        : "+f"(c[0]), "+f"(c[1]), "+f"(c[2]), "+f"(c[3])
        : "r"(a[0]), "r"(a[1]), "r"(a[2]), "r"(a[3]), "r"(b[0]), "r"(b[1]));
}

__device__ __forceinline__ void cpasync16(uint32_t s, const void* g) {
    asm volatile("cp.async.cg.shared.global [%0], [%1], 16;" :: "r"(s), "l"(g));
}

// swizzled in-tile offset for (row, 16B-chunk)
__device__ __forceinline__ uint32_t swz(int row, int ch) {
    return (uint32_t)(row * 64 + ((ch ^ ((row >> 1) & 3)) << 4));
}

// ---------------------------------------------------------------------------
// Fused QKV projection.  Grid (18, 128); n0 selects output + pass count:
//   n0 <  768 : Q hi/lo (3-pass)   n0 < 1536 : K hi/lo (3-pass)
//   else      : V^T hi  (2-pass)
// 3-stage cp.async pipeline, swizzled smem.
// ---------------------------------------------------------------------------
__global__ void __launch_bounds__(128, 2)
proj_fused(const f16* __restrict__ Ah, const f16* __restrict__ Al,
           const f16* __restrict__ Bh, const f16* __restrict__ Bl,
           f16* __restrict__ Qh, f16* __restrict__ Ql,
           f16* __restrict__ Kh, f16* __restrict__ Kl,
           f16* __restrict__ Vt)
{
    extern __shared__ char smem[];
    const int tid = threadIdx.x, lane = tid & 31, wid = tid >> 5;
    const int m0 = blockIdx.y * 128, n0 = blockIdx.x * 128;
    const int warp_m = wid & 1, warp_n = wid >> 1;
    const bool three = (n0 < 1536);

    const char* pAh = (const char*)Ah;
    const char* pAl = (const char*)Al;
    const char* pBh = (const char*)Bh;
    const char* pBl = (const char*)Bl;

    const uint32_t sb = smem_u32(smem);
    const uint32_t rowbytes = DIM * 2;

    float acc[4][8][4];
#pragma unroll
    for (int t = 0; t < 4; t++)
#pragma unroll
        for (int j = 0; j < 8; j++)
#pragma unroll
            for (int c = 0; c < 4; c++) acc[t][j][c] = 0.0f;

#define PISSUE(kc, buf)                                                          \
    {                                                                            \
        uint32_t s0 = sb + (buf) * STB3;                                         \
        uint32_t kcb = (uint32_t)(kc) * 64;                                      \
        _Pragma("unroll")                                                        \
        for (int i = 0; i < 4; i++) {                                            \
            int c = tid + i * 128;                                               \
            int r = c >> 2, ch = c & 3;                                          \
            size_t goA = (size_t)(m0 + r) * rowbytes + kcb + ch * 16;            \
            size_t goB = (size_t)(n0 + r) * rowbytes + kcb + ch * 16;            \
            uint32_t so = swz(r, ch);                                            \
            cpasync16(s0 + 0 * TILE + so, pAh + goA);                            \
            cpasync16(s0 + 1 * TILE + so, pAl + goA);                            \
            cpasync16(s0 + 2 * TILE + so, pBh + goB);                            \
            if (three) cpasync16(s0 + 3 * TILE + so, pBl + goB);                 \
        }                                                                        \
        asm volatile("cp.async.commit_group;" ::: "memory");                     \
    }

    PISSUE(0, 0);
    PISSUE(1, 1);

    const int nch = DIM >> 5;   // 24
    int cb = 0, ib = 2;
    for (int kc = 0; kc < nch; kc++) {
        asm volatile("cp.async.wait_group 1;" ::: "memory");
        __syncthreads();

        const int knext = kc + 2;
        if (knext < nch) PISSUE(knext, ib);
        ib = (ib + 1 == 3) ? 0 : ib + 1;

        const uint32_t sA = sb + cb * STB3;
        cb = (cb + 1 == 3) ? 0 : cb + 1;

#pragma unroll
        for (int ks = 0; ks < 2; ks++) {
            uint32_t afh[4][4], afl[4][4];

            const int ra0 = warp_m * 64 + (lane & 15);
            const int ca = ks * 2 + (lane >> 4);
#pragma unroll
            for (int t = 0; t < 4; t++) {
                uint32_t ad = sA + swz(ra0 + t * 16, ca);
                ldmx4(afh[t], ad);
                ldmx4(afl[t], ad + TILE);
            }

            const int rb0 = warp_n * 64 + (lane >> 4) * 8 + (lane & 7);
            const int cbk = ks * 2 + ((lane >> 3) & 1);
#pragma unroll
            for (int jp = 0; jp < 4; jp++) {
                uint32_t bd = sA + 2 * TILE + swz(rb0 + jp * 16, cbk);
                uint32_t rh[4];
                ldmx4(rh, bd);
                const int j0 = jp * 2, j1 = jp * 2 + 1;
#pragma unroll
                for (int t = 0; t < 4; t++) {
                    mma_f16(acc[t][j0], afh[t], rh + 0);
                    mma_f16(acc[t][j1], afh[t], rh + 2);
                }
                if (three) {
                    uint32_t rl[4];
                    ldmx4(rl, bd + TILE);
#pragma unroll
                    for (int t = 0; t < 4; t++) {
                        mma_f16(acc[t][j0], afh[t], rl + 0);
                        mma_f16(acc[t][j1], afh[t], rl + 2);
                    }
                }
#pragma unroll
                for (int t = 0; t < 4; t++) {
                    mma_f16(acc[t][j0], afl[t], rh + 0);
                    mma_f16(acc[t][j1], afl[t], rh + 2);
                }
            }
        }
        __syncthreads();
    }
#undef PISSUE

    // ---------------- epilogue dispatch ----------------
    const int rbase = warp_m * 64 + (lane >> 2);
    const int cbase = warp_n * 64 + (lane & 3) * 2;

    if (three) {
        f16* Oh = (n0 < 768) ? Qh : Kh;
        f16* Ol = (n0 < 768) ? Ql : Kl;
        const int nc0 = (n0 < 768) ? n0 : n0 - 768;
#pragma unroll
        for (int t = 0; t < 4; t++)
#pragma unroll
            for (int j = 0; j < 8; j++)
#pragma unroll
                for (int h = 0; h < 2; h++) {
                    int rr = m0 + rbase + t * 16 + h * 8;
                    int cc = nc0 + cbase + j * 8;
                    float x0 = acc[t][j][h * 2 + 0], x1 = acc[t][j][h * 2 + 1];
                    f16 h0 = __float2half(x0), h1 = __float2half(x1);
                    f16 l0 = __float2half(x0 - __half2float(h0));
                    f16 l1 = __float2half(x1 - __half2float(h1));
                    *(__half2*)(Oh + (size_t)rr * DIM + cc) = __halves2half2(h0, h1);
                    *(__half2*)(Ol + (size_t)rr * DIM + cc) = __halves2half2(l0, l1);
                }
    } else {
        float* st = (float*)smem;
#pragma unroll
        for (int t = 0; t < 4; t++)
#pragma unroll
            for (int j = 0; j < 8; j++)
#pragma unroll
                for (int h = 0; h < 2; h++) {
                    int rr = rbase + t * 16 + h * 8;
                    int cc = cbase + j * 8;
                    st[(size_t)rr * 129 + cc + 0] = acc[t][j][h * 2 + 0];
                    st[(size_t)rr * 129 + cc + 1] = acc[t][j][h * 2 + 1];
                }
        __syncthreads();
        const int nv0 = n0 - 1536;
        for (int idx = tid; idx < 128 * 128; idx += 128) {
            int nl = idx >> 7, ml = idx & 127;
            int mg = m0 + ml;
            int b = mg >> 11, mloc = mg & 2047;
            float x = st[(size_t)ml * 129 + nl];
            size_t o = (size_t)b * DIM * SEQ + (size_t)(nv0 + nl) * SEQ + mloc;
            Vt[o] = __float2half(x);
        }
    }
}

// ---------------------------------------------------------------------------
// Batched GEMM: NPASS=3 (scores: AhBh+AhBl+AlBh, 3-stage) and
//               NPASS=1 (PV: AhBh only, 2 tiles/stage, 5-stage), fp32 out.
// ---------------------------------------------------------------------------
template <int NPASS>
__global__ void __launch_bounds__(128, 2)
gemm_mma(const f16* __restrict__ Ah, const f16* __restrict__ Al,
         const f16* __restrict__ Bh, const f16* __restrict__ Bl,
         float* __restrict__ O,
         int K, long batchA, long batchB, long batchC, int ldC)
{
    constexpr int NSTAGE = (NPASS == 1) ? 5 : 3;
    constexpr int STB    = (NPASS == 1) ? STB1 : STB3;
    constexpr int BOFF   = (NPASS == 1) ? TILE : 2 * TILE;   // B_HI offset

    extern __shared__ char smem[];
    const int tid = threadIdx.x, lane = tid & 31, wid = tid >> 5;
    const int z = blockIdx.z;
    const int m0 = blockIdx.y * 128, n0 = blockIdx.x * 128;
    const int warp_m = wid & 1, warp_n = wid >> 1;

    const char* pAh = (const char*)(Ah + (size_t)z * batchA);
    const char* pAl = (NPASS >= 2 || NPASS == 3) ? (const char*)(Al + (size_t)z * batchA) : nullptr;
    const char* pBh = (const char*)(Bh + (size_t)z * batchB);
    const char* pBl = (NPASS == 3) ? (const char*)(Bl + (size_t)z * batchB) : nullptr;
    // NPASS==3 also uses Al
    const char* pAl3 = (NPASS == 3) ? (const char*)(Al + (size_t)z * batchA) : pAl;

    const uint32_t sb = smem_u32(smem);
    const uint32_t rowbytes = (uint32_t)K * 2;

    float acc[4][8][4];
#pragma unroll
    for (int t = 0; t < 4; t++)
#pragma unroll
        for (int j = 0; j < 8; j++)
#pragma unroll
            for (int c = 0; c < 4; c++) acc[t][j][c] = 0.0f;

    const int nch = K >> 5;

#define ISSUE(kc, buf)                                                           \
    {                                                                            \
        uint32_t s0 = sb + (buf) * STB;                                          \
        uint32_t kcb = (uint32_t)(kc) * 64;                                      \
        _Pragma("unroll")                                                        \
        for (int i = 0; i < 4; i++) {                                            \
            int c = tid + i * 128;                                               \
            int r = c >> 2, ch = c & 3;                                          \
            size_t goA = (size_t)(m0 + r) * rowbytes + kcb + ch * 16;            \
            size_t goB = (size_t)(n0 + r) * rowbytes + kcb + ch * 16;            \
            uint32_t so = swz(r, ch);                                            \
            cpasync16(s0 + so, pAh + goA);                                       \
            if (NPASS == 3) cpasync16(s0 + TILE + so, pAl3 + goA);               \
            cpasync16(s0 + BOFF + so, pBh + goB);                                \
            if (NPASS == 3) cpasync16(s0 + 3 * TILE + so, pBl + goB);            \
        }                                                                        \
        asm volatile("cp.async.commit_group;" ::: "memory");                     \
    }

#pragma unroll
    for (int p = 0; p < NSTAGE - 1; p++) ISSUE(p, p);

    int cb = 0, ib = NSTAGE - 1;
    for (int kc = 0; kc < nch; kc++) {
        asm volatile("cp.async.wait_group %0;" :: "n"(NSTAGE - 2) : "memory");
        __syncthreads();

        const int knext = kc + NSTAGE - 1;
        if (knext < nch) ISSUE(knext, ib);
        ib = (ib + 1 == NSTAGE) ? 0 : ib + 1;

        const uint32_t sA = sb + cb * STB;
        cb = (cb + 1 == NSTAGE) ? 0 : cb + 1;

#pragma unroll
        for (int ks = 0; ks < 2; ks++) {
            uint32_t afh[4][4], afl[4][4];

            const int ra0 = warp_m * 64 + (lane & 15);
            const int ca = ks * 2 + (lane >> 4);
#pragma unroll
            for (int t = 0; t < 4; t++) {
                uint32_t ad = sA + swz(ra0 + t * 16, ca);
                ldmx4(afh[t], ad);
                if (NPASS == 3) ldmx4(afl[t], ad + TILE);
            }

            const int rb0 = warp_n * 64 + (lane >> 4) * 8 + (lane & 7);
            const int cbk = ks * 2 + ((lane >> 3) & 1);
#pragma unroll
            for (int jp = 0; jp < 4; jp++) {
                uint32_t bd = sA + BOFF + swz(rb0 + jp * 16, cbk);
                uint32_t rh[4];
                ldmx4(rh, bd);
                const int j0 = jp * 2, j1 = jp * 2 + 1;
#pragma unroll
                for (int t = 0; t < 4; t++) {
                    mma_f16(acc[t][j0], afh[t], rh + 0);
                    mma_f16(acc[t][j1], afh[t], rh + 2);
                }
                if (NPASS == 3) {
                    uint32_t rl[4];
                    ldmx4(rl, bd + TILE);
#pragma unroll
                    for (int t = 0; t < 4; t++) {
                        mma_f16(acc[t][j0], afh[t], rl + 0);
                        mma_f16(acc[t][j1], afh[t], rl + 2);
                    }
#pragma unroll
                    for (int t = 0; t < 4; t++) {
                        mma_f16(acc[t][j0], afl[t], rh + 0);
                        mma_f16(acc[t][j1], afl[t], rh + 2);
                    }
                }
            }
        }
        __syncthreads();
    }
#undef ISSUE

    // fp32 epilogue
    const int rbase = warp_m * 64 + (lane >> 2);
    const int cbase = warp_n * 64 + (lane & 3) * 2;
    float* C = O + (size_t)z * batchC;
#pragma unroll
    for (int t = 0; t < 4; t++)
#pragma unroll
        for (int j = 0; j < 8; j++) {
            int rr = m0 + rbase + t * 16;
            int cc = n0 + cbase + j * 8;
            *(float2*)(C + (size_t)rr * ldC + cc) =
                make_float2(acc[t][j][0], acc[t][j][1]);
            *(float2*)(C + (size_t)(rr + 8) * ldC + cc) =
                make_float2(acc[t][j][2], acc[t][j][3]);
        }
}

// ---------------- prep kernels ----------------------------------------------
__global__ void split_kernel(const float* __restrict__ X,
                             f16* __restrict__ H, f16* __restrict__ L, int n)
{
    int i = blockIdx.x * 256 + threadIdx.x;
    if (i < n) {
        float x = X[i];
        f16 h = __float2half(x);
        H[i] = h;
        L[i] = __float2half(x - __half2float(h));
    }
}

__global__ void wsplit_kernel(const float* __restrict__ W,
                              f16* __restrict__ TH, f16* __restrict__ TL)
{
    int i = blockIdx.x * 256 + threadIdx.x;   // out idx f*DIM + d
    int f = i / DIM, d = i % DIM;
    float x = W[d * DIM + f];
    f16 h = __float2half(x);
    TH[i] = h;
    TL[i] = __float2half(x - __half2float(h));
}

// ---------------- softmax: S fp32 -> P fp16 hi (vectorized) -----------------
__global__ void __launch_bounds__(256)
softmax_kernel(const float* __restrict__ S, f16* __restrict__ Ph)
{
    const int row = blockIdx.x;
    const float4* p4 = (const float4*)(S + (size_t)row * SEQ);
    const int tid = threadIdx.x;

    float4 va = p4[tid];
    float4 vb = p4[tid + 256];
    float m = fmaxf(fmaxf(fmaxf(va.x, va.y), fmaxf(va.z, va.w)),
                    fmaxf(fmaxf(vb.x, vb.y), fmaxf(vb.z, vb.w)));

    __shared__ float red[256];
    red[tid] = m;
    __syncthreads();
#pragma unroll
    for (int s = 128; s > 0; s >>= 1) {
        if (tid < s) red[tid] = fmaxf(red[tid], red[tid + s]);
        __syncthreads();
    }
    m = red[0];
    __syncthreads();

    va.x = expf(va.x - m); va.y = expf(va.y - m);
    va.z = expf(va.z - m); va.w = expf(va.w - m);
    vb.x = expf(vb.x - m); vb.y = expf(vb.y - m);
    vb.z = expf(vb.z - m); vb.w = expf(vb.w - m);
    float sum = (va.x + va.y) + (va.z + va.w) + (vb.x + vb.y) + (vb.z + vb.w);

    red[tid] = sum;
    __syncthreads();
#pragma unroll
    for (int s = 128; s > 0; s >>= 1) {
        if (tid < s) red[tid] += red[tid + s];
        __syncthreads();
    }
    const float inv = 1.0f / red[0];

    __half2* ph2 = (__half2*)(Ph + (size_t)row * SEQ);
#pragma unroll
    for (int half = 0; half < 2; half++) {
        float4 v = half ? vb : va;
        int base = (half ? (tid + 256) : tid) * 2;
        ph2[base + 0] = __halves2half2(__float2half(v.x * inv),
                                       __float2half(v.y * inv));
        ph2[base + 1] = __halves2half2(__float2half(v.z * inv),
                                       __float2half(v.w * inv));
    }
}

// ---------------------------------------------------------------------------
extern "C" void kernel_launch(void* const* d_in, const int* in_sizes, int n_in,
                              void* d_out, int out_size)
{
    const float* X  = (const float*)d_in[0];
    const float* Wq = (const float*)d_in[1];
    const float* Wk = (const float*)d_in[2];
    const float* Wv = (const float*)d_in[3];
    float* out = (float*)d_out;

    f16 *xh, *xl, *wth, *wtl, *qh, *ql, *kh, *kl, *vth, *ph;
    float* s;
    cudaGetSymbolAddress((void**)&xh, g_xh);
    cudaGetSymbolAddress((void**)&xl, g_xl);
    cudaGetSymbolAddress((void**)&wth, g_wth);
    cudaGetSymbolAddress((void**)&wtl, g_wtl);
    cudaGetSymbolAddress((void**)&qh, g_qh);
    cudaGetSymbolAddress((void**)&ql, g_ql);
    cudaGetSymbolAddress((void**)&kh, g_kh);
    cudaGetSymbolAddress((void**)&kl, g_kl);
    cudaGetSymbolAddress((void**)&vth, g_vth);
    cudaGetSymbolAddress((void**)&ph, g_ph);
    cudaGetSymbolAddress((void**)&s, g_s);

    cudaFuncSetAttribute(proj_fused, cudaFuncAttributeMaxDynamicSharedMemorySize, SMEMSZ3);
    cudaFuncSetAttribute(gemm_mma<3>, cudaFuncAttributeMaxDynamicSharedMemorySize, SMEMSZ3);
    cudaFuncSetAttribute(gemm_mma<1>, cudaFuncAttributeMaxDynamicSharedMemorySize, SMEMSZ1);

    const int nx = MTOT * DIM;
    split_kernel<<<nx / 256, 256>>>(X, xh, xl, nx);
    wsplit_kernel<<<(DIM * DIM) / 256, 256>>>(Wq, wth + 0 * DIM * DIM, wtl + 0 * DIM * DIM);
    wsplit_kernel<<<(DIM * DIM) / 256, 256>>>(Wk, wth + 1 * DIM * DIM, wtl + 1 * DIM * DIM);
    wsplit_kernel<<<(DIM * DIM) / 256, 256>>>(Wv, wth + 2 * DIM * DIM, wtl + 2 * DIM * DIM);

    // Fused QKV projection: grid 18 x 128
    dim3 gp(3 * DIM / 128, MTOT / 128, 1);
    proj_fused<<<gp, 128, SMEMSZ3>>>(xh, xl, wth, wtl, qh, ql, kh, kl, vth);

    // Scores: per batch S = Q * K^T, [2048,2048], K=768 (3-pass, 3-stage)
    dim3 gs(SEQ / 128, SEQ / 128, BSZ);
    gemm_mma<3><<<gs, 128, SMEMSZ3>>>(qh, ql, kh, kl, s, DIM,
                                      (long)SEQ * DIM, (long)SEQ * DIM,
                                      (long)SEQ * SEQ, SEQ);

    softmax_kernel<<<BSZ * SEQ, 256>>>(s, ph);

    // Out: per batch O = P * (V^T)^T, [2048,768], K=2048 (1-pass, 5-stage)
    dim3 go(DIM / 128, SEQ / 128, BSZ);
    gemm_mma<1><<<go, 128, SMEMSZ1>>>(ph, nullptr, vth, nullptr, out, SEQ,
                                      (long)SEQ * SEQ, (long)DIM * SEQ,
                                      (long)SEQ * DIM, DIM);
}